// round 12
// baseline (speedup 1.0000x reference)
#include <cuda_runtime.h>
#include <cuda_fp16.h>
#include <cuda_bf16.h>
#include <math.h>
#include <stdint.h>

// Problem constants
#define Bq   8
#define Lq   1024
#define Eq   512
#define Hq   8
#define FFq  2048
#define Mq   (Bq*Lq)          // 8192 tokens

typedef __half        fp16;
typedef __nv_bfloat16 bf16;

// ---------------- scratch (static device globals; allocation-free) ----------
__device__ float g_x [Mq*Eq];        // current activations (fp32, residual path)
__device__ float g_sv[Bq*Hq*Lq];     // per-(b,h,i) 0.125/sum(exp)
__device__ float g_t [Mq*Eq];        // sa / ff temp (fp32)
__device__ bf16  g_P [(size_t)Bq*Hq*Lq*Lq];  // per-head exp(logits), bf16, causal tiles

// fp16 buffers (plain quantized)
__device__ fp16 g_xh [Mq*Eq];
__device__ fp16 g_qk [Mq*1024];
__device__ fp16 g_aw [(size_t)Bq*Lq*Lq];
__device__ fp16 g_xt [Bq*Eq*Lq];
__device__ fp16 g_h  [Mq*FFq];
__device__ fp16 g_Wq [4*1024*512];
__device__ fp16 g_W1 [4*2048*512];
__device__ fp16 g_W2 [4*512*2048];

// ---------------- helpers ------------------------------------------------------
__device__ __forceinline__ float warp_sum(float s){
    #pragma unroll
    for (int o=16;o;o>>=1) s += __shfl_xor_sync(0xffffffffu, s, o);
    return s;
}
__device__ __forceinline__ uint32_t hquant(float x0, float x1){
    return (uint32_t)__half_as_ushort(__float2half_rn(x0)) |
           ((uint32_t)__half_as_ushort(__float2half_rn(x1)) << 16);
}
__device__ __forceinline__ uint32_t bpack(float x0, float x1){
    __nv_bfloat162 b = __floats2bfloat162_rn(x0, x1);
    return *(uint32_t*)&b;
}
__device__ __forceinline__ uint32_t smem_u32(const void* p){
    uint32_t a;
    asm("{ .reg .u64 t; cvta.to.shared.u64 t, %1; cvt.u32.u64 %0, t; }" : "=r"(a) : "l"(p));
    return a;
}
__device__ __forceinline__ void cp16(uint32_t dst, const void* src){
    asm volatile("cp.async.cg.shared.global [%0], [%1], 16;" :: "r"(dst), "l"(src));
}
#define CP_COMMIT() asm volatile("cp.async.commit_group;" ::: "memory")
#define CP_WAIT0()  asm volatile("cp.async.wait_group 0;" ::: "memory")
#define CP_WAIT1()  asm volatile("cp.async.wait_group 1;" ::: "memory")

#define LDSM_X4(r, addr) \
    asm volatile("ldmatrix.sync.aligned.m8n8.x4.shared.b16 {%0,%1,%2,%3}, [%4];" \
        : "=r"((r)[0]), "=r"((r)[1]), "=r"((r)[2]), "=r"((r)[3]) : "r"(addr))

__device__ __forceinline__ void mma16816(float* c, const uint32_t* a, const uint32_t* b){
    asm volatile(
        "mma.sync.aligned.m16n8k16.row.col.f32.f16.f16.f32 "
        "{%0,%1,%2,%3}, {%4,%5,%6,%7}, {%8,%9}, {%0,%1,%2,%3};\n"
        : "+f"(c[0]), "+f"(c[1]), "+f"(c[2]), "+f"(c[3])
        : "r"(a[0]), "r"(a[1]), "r"(a[2]), "r"(a[3]), "r"(b[0]), "r"(b[1]));
}

// ============================================================================
// Quantization kernels: fp32 -> fp16 (optionally keep fp32 copy)
// ============================================================================
__global__ __launch_bounds__(256) void quant_arr(
    const float* __restrict__ in, fp16* __restrict__ oh, int n4)
{
    int i = blockIdx.x*256 + threadIdx.x;
    if (i >= n4) return;
    float4 v = ((const float4*)in)[i];
    ((uint2*)oh)[i] = make_uint2(hquant(v.x, v.y), hquant(v.z, v.w));
}

__global__ __launch_bounds__(256) void quant_copy(
    const float* __restrict__ in, float* __restrict__ out,
    fp16* __restrict__ oh, int n4)
{
    int i = blockIdx.x*256 + threadIdx.x;
    if (i >= n4) return;
    float4 v = ((const float4*)in)[i];
    ((float4*)out)[i] = v;
    ((uint2*)oh)[i] = make_uint2(hquant(v.x, v.y), hquant(v.z, v.w));
}

// ============================================================================
// Tensor-core GEMM NT, fp16 x fp16, fp32 accumulate.
// Tile 128(M) x 256(N), BK=64, 256 threads (2x4 warps, 64x64 each),
// 3-stage cp.async ring, ONE __syncthreads per 64-k chunk, ldmatrix frags.
// Smem rows: 64 fp16 (128B) + 16B pad = 144B (conflict-free, validated).
//   C[M,N] = A[M,K] * B[N,K]^T (+bias, relu), batched via z.
// ============================================================================
#define SA_U32   (128*36)               // A stage: 128 rows * 36 u32
#define SB_U32   (256*36)               // B stage: 256 rows * 36 u32
#define STG_U32  (SA_U32 + SB_U32)      // 13824
#define GEMM_SMEM (3 * STG_U32 * 4)     // 165888 B

template<int RELU, int WF32, int WH16>
__global__ __launch_bounds__(256, 1) void mma_gemm2(
    const fp16* __restrict__ Ah, const fp16* __restrict__ Bh,
    const float* __restrict__ bias,
    float* __restrict__ C, fp16* __restrict__ Ch,
    int M, int N, int K, long sA, long sB, long sC, int causal)
{
    extern __shared__ uint32_t sg[];
    const int bm = blockIdx.y * 128, bn = blockIdx.x * 256;
    const fp16* Abh = Ah + (size_t)blockIdx.z * sA;
    const fp16* Bbh = Bh + (size_t)blockIdx.z * sB;

    const int t    = threadIdx.x;
    const int lane = t & 31, wid = t >> 5;
    const int wm   = wid >> 2, wn = wid & 3;
    const int gid  = lane >> 2, tig = lane & 3;
    const int fr   = t >> 1, half = t & 1;

    float acc[4][8][4];
    #pragma unroll
    for (int i=0;i<4;i++)
        #pragma unroll
        for (int j=0;j<8;j++)
            #pragma unroll
            for (int q=0;q<4;q++) acc[i][j][q] = 0.f;

    const uint32_t sbase = smem_u32(sg);
    // cp.async fill addresses: each thread fills 64B of A row fr, 64B of B rows fr, fr+128
    const uint32_t da  = sbase + (uint32_t)(fr*144) + (uint32_t)half*64;
    const uint32_t db0 = sbase + (uint32_t)(SA_U32*4) + (uint32_t)(fr*144) + (uint32_t)half*64;
    const uint32_t db1 = db0 + 128u*144u;
    const fp16* ga  = Abh + (size_t)(bm+fr)*K + half*32;
    const fp16* gb0 = Bbh + (size_t)(bn+fr)*K + half*32;
    const fp16* gb1 = Bbh + (size_t)(bn+128+fr)*K + half*32;

    // ldmatrix base addresses (144B row stride)
    const uint32_t aB = sbase + (uint32_t)((wm*64 + (lane & 15))*144) + (uint32_t)(lane >> 4)*16;
    const uint32_t bB = sbase + (uint32_t)(SA_U32*4) +
        (uint32_t)((wn*64 + ((lane >> 4) << 3) + (lane & 7))*144) +
        (uint32_t)((lane >> 3) & 1)*16;

    const int kend = causal ? (bm + 128) : K;
    const int nch  = kend >> 6;

    #define G_ISSUE(ch_) do{ \
        const uint32_t st_ = (uint32_t)((ch_) % 3) * (STG_U32*4); \
        const fp16* A0_ = ga  + ((ch_) << 6); \
        const fp16* B0_ = gb0 + ((ch_) << 6); \
        const fp16* B1_ = gb1 + ((ch_) << 6); \
        cp16(da  + st_,      A0_);       cp16(da  + st_ + 16, A0_ + 8); \
        cp16(da  + st_ + 32, A0_ + 16);  cp16(da  + st_ + 48, A0_ + 24); \
        cp16(db0 + st_,      B0_);       cp16(db0 + st_ + 16, B0_ + 8); \
        cp16(db0 + st_ + 32, B0_ + 16);  cp16(db0 + st_ + 48, B0_ + 24); \
        cp16(db1 + st_,      B1_);       cp16(db1 + st_ + 16, B1_ + 8); \
        cp16(db1 + st_ + 32, B1_ + 16);  cp16(db1 + st_ + 48, B1_ + 24); \
        CP_COMMIT(); }while(0)

    if (nch > 0) G_ISSUE(0);
    if (nch > 1) G_ISSUE(1);

    for (int ch = 0; ch < nch; ch++){
        if (ch + 1 < nch) CP_WAIT1(); else CP_WAIT0();
        __syncthreads();                 // stage ch visible; prior compute done
        if (ch + 2 < nch) G_ISSUE(ch+2); // overwrites stage read 2 iters ago

        const uint32_t so = (uint32_t)(ch % 3) * (STG_U32*4);
        #pragma unroll
        for (int ks=0; ks<4; ks++){
            uint32_t ah[4][4], bf[4][4];
            #pragma unroll
            for (int mi=0;mi<4;mi++)
                LDSM_X4(ah[mi], aB + so + (uint32_t)mi*(16*144) + (uint32_t)ks*32);
            #pragma unroll
            for (int np=0;np<4;np++)
                LDSM_X4(bf[np], bB + so + (uint32_t)np*(16*144) + (uint32_t)ks*32);
            #pragma unroll
            for (int mi=0;mi<4;mi++){
                #pragma unroll
                for (int ni=0;ni<8;ni++){
                    uint32_t bb[2] = { bf[ni>>1][(ni&1)*2], bf[ni>>1][(ni&1)*2+1] };
                    mma16816(acc[mi][ni], ah[mi], bb);
                }
            }
        }
    }
    #undef G_ISSUE

    float* Cb  = WF32 ? C  + (size_t)blockIdx.z * sC : nullptr;
    fp16*  Chb = WH16 ? Ch + (size_t)blockIdx.z * sC : nullptr;
    #pragma unroll
    for (int mi=0;mi<4;mi++){
        int row = bm + wm*64 + mi*16 + gid;
        #pragma unroll
        for (int ni=0;ni<8;ni++){
            int col = bn + wn*64 + ni*8 + tig*2;
            float2 v0 = make_float2(acc[mi][ni][0], acc[mi][ni][1]);
            float2 v1 = make_float2(acc[mi][ni][2], acc[mi][ni][3]);
            if (bias){
                float2 bb = *(const float2*)(bias + col);
                v0.x += bb.x; v0.y += bb.y; v1.x += bb.x; v1.y += bb.y;
            }
            if (RELU){
                v0.x=fmaxf(v0.x,0.f); v0.y=fmaxf(v0.y,0.f);
                v1.x=fmaxf(v1.x,0.f); v1.y=fmaxf(v1.y,0.f);
            }
            if (WF32){
                *(float2*)(Cb + (size_t)row    *N + col) = v0;
                *(float2*)(Cb + (size_t)(row+8)*N + col) = v1;
            }
            if (WH16){
                *(uint32_t*)(Chb + (size_t)row    *N + col) = hquant(v0.x, v0.y);
                *(uint32_t*)(Chb + (size_t)(row+8)*N + col) = hquant(v1.x, v1.y);
            }
        }
    }
}

// ============================================================================
// Fused attention exp kernel, fp16, 3-stage cp.async K ring, ldmatrix frags:
// per (b,h,i0): logits = Q*K^T/8; E = exp; row sums -> sinv;
// store E (bf16) to P for causal tiles.
// Dyn smem: sQ (4608 u32) + 3 K stages (4608 u32 each) = 73728 B
// ============================================================================
#define ATTN_SMEM (4*4608*4)
__global__ __launch_bounds__(256) void attn_exp(
    const fp16* __restrict__ qk,
    bf16* __restrict__ P, float* __restrict__ sinv)
{
    extern __shared__ uint32_t smx[];
    uint32_t* sQh = smx;
    uint32_t* sK  = smx + 4608;
    __shared__ float sred[128];

    const int bh = blockIdx.x;
    const int ti = blockIdx.y;
    const int i0 = ti * 128;
    const int b  = bh >> 3, h = bh & 7;
    const size_t qoff = (size_t)(b*Lq)*1024 + h*64;

    const int t = threadIdx.x;
    const int lane = t & 31, wid = t >> 5;
    const int wm = wid >> 2, wn = wid & 3;
    const int gid = lane >> 2, tig = lane & 3;
    const int fr = t >> 1, half = t & 1;

    if (t < 128) sred[t] = 0.f;

    const uint32_t dk = smem_u32(sK) + fr*144 + half*64;
    const fp16* gk = qk + qoff + 512 + (size_t)fr*1024 + half*32;

    #define K_ISSUE(jt_) do{ \
        const uint32_t st_ = (uint32_t)((jt_) % 3) * 18432; \
        const fp16* g_ = gk + (size_t)(jt_)*128*1024; \
        cp16(dk + st_,      g_);       cp16(dk + st_ + 16, g_ + 8); \
        cp16(dk + st_ + 32, g_ + 16);  cp16(dk + st_ + 48, g_ + 24); \
        CP_COMMIT(); }while(0)

    K_ISSUE(0);
    K_ISSUE(1);

    // load Q tile [128 x 64]
    {
        const uint4* sh = (const uint4*)(qk + qoff + (size_t)(i0+fr)*1024 + half*32);
        uint4* dh = (uint4*)(sQh + fr*36 + half*16);
        dh[0]=sh[0]; dh[1]=sh[1]; dh[2]=sh[2]; dh[3]=sh[3];
    }

    // ldmatrix base addresses (stride 36 u32 = 144 B)
    const uint32_t qB = smem_u32(sQh) +
        (uint32_t)((wm*64 + (lane & 15))*36)*4 + (uint32_t)(lane >> 4)*16;
    const uint32_t kB = smem_u32(sK) +
        (uint32_t)((wn*32 + ((lane >> 4) << 3) + (lane & 7))*36)*4 +
        (uint32_t)((lane >> 3) & 1)*16;

    float rsum[4][2];
    #pragma unroll
    for (int mi=0;mi<4;mi++){ rsum[mi][0]=0.f; rsum[mi][1]=0.f; }

    for (int jt = 0; jt < Lq/128; jt++){
        if (jt + 1 < Lq/128) CP_WAIT1(); else CP_WAIT0();
        __syncthreads();
        if (jt + 2 < Lq/128) K_ISSUE(jt+2);

        const uint32_t so = (uint32_t)(jt % 3) * 18432;
        float acc[4][4][4];
        #pragma unroll
        for (int i=0;i<4;i++)
            #pragma unroll
            for (int j=0;j<4;j++)
                #pragma unroll
                for (int q=0;q<4;q++) acc[i][j][q] = 0.f;

        #pragma unroll
        for (int ks=0; ks<4; ks++){
            uint32_t ah[4][4], bf[2][4];
            #pragma unroll
            for (int mi=0;mi<4;mi++)
                LDSM_X4(ah[mi], qB + (uint32_t)mi*(16*144) + (uint32_t)ks*32);
            #pragma unroll
            for (int np=0;np<2;np++)
                LDSM_X4(bf[np], kB + so + (uint32_t)np*(16*144) + (uint32_t)ks*32);
            #pragma unroll
            for (int mi=0;mi<4;mi++){
                #pragma unroll
                for (int ni=0;ni<4;ni++){
                    uint32_t bb[2] = { bf[ni>>1][(ni&1)*2], bf[ni>>1][(ni&1)*2+1] };
                    mma16816(acc[mi][ni], ah[mi], bb);
                }
            }
        }

        const int j0 = jt * 128;
        const bool store = (jt <= ti);
        #pragma unroll
        for (int mi=0;mi<4;mi++){
            const int row = i0 + wm*64 + mi*16 + gid;
            #pragma unroll
            for (int ni=0;ni<4;ni++){
                float e0 = __expf(acc[mi][ni][0] * 0.125f);
                float e1 = __expf(acc[mi][ni][1] * 0.125f);
                float e2 = __expf(acc[mi][ni][2] * 0.125f);
                float e3 = __expf(acc[mi][ni][3] * 0.125f);
                rsum[mi][0] += e0 + e1;
                rsum[mi][1] += e2 + e3;
                if (store){
                    const int col = j0 + wn*32 + ni*8 + tig*2;
                    bf16* p0 = P + ((size_t)bh*Lq + row)*Lq + col;
                    *(uint32_t*)p0          = bpack(e0, e1);
                    *(uint32_t*)(p0 + 8*Lq) = bpack(e2, e3);
                }
            }
        }
    }
    #undef K_ISSUE

    #pragma unroll
    for (int mi=0;mi<4;mi++){
        float r0 = rsum[mi][0], r1 = rsum[mi][1];
        r0 += __shfl_xor_sync(0xffffffffu, r0, 1);
        r0 += __shfl_xor_sync(0xffffffffu, r0, 2);
        r1 += __shfl_xor_sync(0xffffffffu, r1, 1);
        r1 += __shfl_xor_sync(0xffffffffu, r1, 2);
        if (tig == 0){
            atomicAdd(&sred[wm*64 + mi*16 + gid    ], r0);
            atomicAdd(&sred[wm*64 + mi*16 + gid + 8], r1);
        }
    }
    __syncthreads();
    if (t < 128)
        sinv[(size_t)bh*Lq + i0 + t] = 0.125f / sred[t];
}

// ============================================================================
// Fused head-average + second softmax (A never materialized):
// per (b,i): a[j] = sum_h P[b,h,i,j]*sinv[b,h,i];
// W = softmax_{j<=i}( a + exp((j-i)*0.1) ); writes fp16 W.
// ============================================================================
__global__ __launch_bounds__(256) void make_w2(
    const bf16* __restrict__ P, const float* __restrict__ sinv,
    fp16* __restrict__ Wh)
{
    const int row = blockIdx.x;            // b*1024 + i
    const int b = row >> 10, i = row & 1023;
    const int t = threadIdx.x;
    __shared__ float sv8[8];
    if (t < 8) sv8[t] = sinv[(size_t)(b*8 + t)*Lq + i];
    __syncthreads();

    const int j0 = t*4;
    float v[4] = {0.f,0.f,0.f,0.f};
    float s = 0.f;
    if (j0 <= i){
        float a[4] = {0.f,0.f,0.f,0.f};
        const bf16* pb = P + ((size_t)(b*8)*Lq + i)*Lq + j0;
        #pragma unroll
        for (int h=0; h<8; h++){
            const uint2 pv = *(const uint2*)(pb + (size_t)h*Lq*Lq);
            const float sc = sv8[h];
            float2 f0 = __bfloat1622float2(*(const __nv_bfloat162*)&pv.x);
            float2 f1 = __bfloat1622float2(*(const __nv_bfloat162*)&pv.y);
            a[0] = fmaf(f0.x, sc, a[0]); a[1] = fmaf(f0.y, sc, a[1]);
            a[2] = fmaf(f1.x, sc, a[2]); a[3] = fmaf(f1.y, sc, a[3]);
        }
        #pragma unroll
        for (int u=0;u<4;u++){
            int j = j0 + u;
            if (j <= i){
                float pos = __expf((float)(j - i) * 0.1f);
                v[u] = __expf(a[u] + pos);
                s += v[u];
            }
        }
    }
    s = warp_sum(s);
    __shared__ float red[8];
    if ((t & 31) == 0) red[t >> 5] = s;
    __syncthreads();
    float tot = 0.f;
    #pragma unroll
    for (int w=0;w<8;w++) tot += red[w];
    float inv = 1.f / tot;
    *(uint2*)(Wh + (size_t)row*Lq + j0) =
        make_uint2(hquant(v[0]*inv, v[1]*inv), hquant(v[2]*inv, v[3]*inv));
}

// ============================================================================
// Batched transpose + quantize: xt[b][e][l] = fp16(x[b][l][e])
// ============================================================================
__global__ __launch_bounds__(256) void transpose_x(
    const float* __restrict__ x, fp16* __restrict__ xt)
{
    __shared__ float tile[32][33];
    const int b  = blockIdx.z;
    const int l0 = blockIdx.y * 32, e0 = blockIdx.x * 32;
    const float* xp = x + (size_t)b * Lq * Eq;
    const int tx = threadIdx.x, ty = threadIdx.y;
    #pragma unroll
    for (int j=0;j<32;j+=8)
        tile[ty+j][tx] = xp[(size_t)(l0+ty+j)*Eq + e0 + tx];
    __syncthreads();
    const size_t base = (size_t)b * Eq * Lq;
    #pragma unroll
    for (int j=0;j<32;j+=8)
        xt[base + (size_t)(e0+ty+j)*Lq + l0 + tx] = __float2half_rn(tile[tx][ty+j]);
}

// ============================================================================
// LayerNorm kernels (one warp per 512-wide row); optional fp16 output
// ============================================================================
template<int WH>
__global__ __launch_bounds__(256) void add_ln2(
    const float* __restrict__ x, const float* __restrict__ y,
    const float* __restrict__ g1, const float* __restrict__ b1,
    const float* __restrict__ g2, const float* __restrict__ b2,
    float* __restrict__ out, fp16* __restrict__ oh)
{
    const int row  = blockIdx.x * 8 + (threadIdx.x >> 5);
    const int lane = threadIdx.x & 31;
    const float* xr = x + (size_t)row * Eq;
    const float* yr = y + (size_t)row * Eq;
    float v[16]; float s = 0.f;
    #pragma unroll
    for (int u=0;u<16;u++){ int c = lane + u*32; v[u] = xr[c] + yr[c]; s += v[u]; }
    s = warp_sum(s);
    float mean = s * (1.0f/Eq);
    float sq = 0.f;
    #pragma unroll
    for (int u=0;u<16;u++){ float d = v[u]-mean; sq += d*d; }
    sq = warp_sum(sq);
    float rstd = rsqrtf(sq*(1.0f/Eq) + 1e-5f);
    float s2 = 0.f;
    #pragma unroll
    for (int u=0;u<16;u++){ int c = lane + u*32; v[u] = (v[u]-mean)*rstd*g1[c] + b1[c]; s2 += v[u]; }
    s2 = warp_sum(s2);
    float m2 = s2 * (1.0f/Eq);
    float q2 = 0.f;
    #pragma unroll
    for (int u=0;u<16;u++){ float d = v[u]-m2; q2 += d*d; }
    q2 = warp_sum(q2);
    float r2 = rsqrtf(q2*(1.0f/Eq) + 1e-5f);
    float* orow = out + (size_t)row * Eq;
    #pragma unroll
    for (int u=0;u<16;u++){
        int c = lane + u*32;
        float o = (v[u]-m2)*r2*g2[c] + b2[c];
        orow[c] = o;
        if (WH) oh[(size_t)row*Eq + c] = __float2half_rn(o);
    }
}

template<int WH>
__global__ __launch_bounds__(256) void add_ln1(
    const float* __restrict__ x, const float* __restrict__ y,
    const float* __restrict__ g, const float* __restrict__ b,
    float* __restrict__ out, fp16* __restrict__ oh)
{
    const int row  = blockIdx.x * 8 + (threadIdx.x >> 5);
    const int lane = threadIdx.x & 31;
    const float* xr = x + (size_t)row * Eq;
    const float* yr = y + (size_t)row * Eq;
    float v[16]; float s = 0.f;
    #pragma unroll
    for (int u=0;u<16;u++){ int c = lane + u*32; v[u] = xr[c] + yr[c]; s += v[u]; }
    s = warp_sum(s);
    float mean = s * (1.0f/Eq);
    float sq = 0.f;
    #pragma unroll
    for (int u=0;u<16;u++){ float d = v[u]-mean; sq += d*d; }
    sq = warp_sum(sq);
    float rstd = rsqrtf(sq*(1.0f/Eq) + 1e-5f);
    float* orow = out + (size_t)row * Eq;
    #pragma unroll
    for (int u=0;u<16;u++){
        int c = lane + u*32;
        float o = (v[u]-mean)*rstd*g[c] + b[c];
        orow[c] = o;
        if (WH) oh[(size_t)row*Eq + c] = __float2half_rn(o);
    }
}

// ============================================================================
// Launch
// ============================================================================
extern "C" void kernel_launch(void* const* d_in, const int* in_sizes, int n_in,
                              void* d_out, int out_size)
{
    const float* input = (const float*)d_in[0];
    const float* Wqkv  = (const float*)d_in[1];
    const float* bqkv  = (const float*)d_in[2];
    const float* W1    = (const float*)d_in[3];
    const float* b1    = (const float*)d_in[4];
    const float* W2    = (const float*)d_in[5];
    const float* b2    = (const float*)d_in[6];
    const float* g1    = (const float*)d_in[7];
    const float* bt1   = (const float*)d_in[8];
    const float* g2    = (const float*)d_in[9];
    const float* bt2   = (const float*)d_in[10];
    const float* g3    = (const float*)d_in[11];
    const float* bt3   = (const float*)d_in[12];

    float *x, *sv, *tb;
    bf16 *P;
    fp16 *xh,*qk,*aw,*xt,*hb,*Wq,*W1f,*W2f;
    cudaGetSymbolAddress((void**)&x,  g_x);
    cudaGetSymbolAddress((void**)&sv, g_sv);
    cudaGetSymbolAddress((void**)&tb, g_t);
    cudaGetSymbolAddress((void**)&P,  g_P);
    cudaGetSymbolAddress((void**)&xh, g_xh);
    cudaGetSymbolAddress((void**)&qk, g_qk);
    cudaGetSymbolAddress((void**)&aw, g_aw);
    cudaGetSymbolAddress((void**)&xt, g_xt);
    cudaGetSymbolAddress((void**)&hb, g_h);
    cudaGetSymbolAddress((void**)&Wq, g_Wq);
    cudaGetSymbolAddress((void**)&W1f,g_W1);
    cudaGetSymbolAddress((void**)&W2f,g_W2);

    cudaFuncSetAttribute(attn_exp, cudaFuncAttributeMaxDynamicSharedMemorySize, ATTN_SMEM);
    cudaFuncSetAttribute(mma_gemm2<0,0,1>, cudaFuncAttributeMaxDynamicSharedMemorySize, GEMM_SMEM);
    cudaFuncSetAttribute(mma_gemm2<0,1,0>, cudaFuncAttributeMaxDynamicSharedMemorySize, GEMM_SMEM);
    cudaFuncSetAttribute(mma_gemm2<1,0,1>, cudaFuncAttributeMaxDynamicSharedMemorySize, GEMM_SMEM);

    // one-time weight quantization + input copy/quant
    for (int d = 0; d < 4; d++){
        int n4 = 1024*512/4;
        quant_arr<<<(n4+255)/256, 256>>>(Wqkv + (size_t)d*1536*512,
                                         Wq + (size_t)d*1024*512, n4);
    }
    {
        int n4 = 4*2048*512/4;
        quant_arr<<<(n4+255)/256, 256>>>(W1, W1f, n4);
        quant_arr<<<(n4+255)/256, 256>>>(W2, W2f, n4);
    }
    {
        int n4 = Mq*Eq/4;
        quant_copy<<<(n4+255)/256, 256>>>(input, x, xh, n4);
    }

    for (int d = 0; d < 4; d++){
        const float* bq = bqkv + (size_t)d * 1536;

        // q|k projection -> fp16 qk (v/out-proj of Wqkv are dead in the reference)
        mma_gemm2<0,0,1><<<dim3(1024/256, Mq/128, 1), 256, GEMM_SMEM>>>(
            xh, Wq + (size_t)d*1024*512,
            bq, nullptr, qk, Mq, 1024, 512, 0, 0, 0, 0);

        // fused logits+exp (stores causal bf16 P, computes sinv)
        attn_exp<<<dim3(Bq*Hq, Lq/128), 256, ATTN_SMEM>>>(qk, P, sv);

        // fused head-average + second softmax -> fp16 attention weights
        make_w2<<<Bq*Lq, 256>>>(P, sv, aw);

        // sa = W @ x: fp16 transpose of x, then NT GEMM w/ causal k cutoff
        transpose_x<<<dim3(Eq/32, Lq/32, Bq), dim3(32,8)>>>(x, xt);
        mma_gemm2<0,1,0><<<dim3(Eq/256, Lq/128, Bq), 256, GEMM_SMEM>>>(
            aw, xt, nullptr, tb, nullptr,
            Lq, Eq, Lq, (long)Lq*Lq, (long)Eq*Lq, (long)Lq*Eq, 1);

        // x = LN2(LN1(x + sa))  (cross-attn block is a double-LN no-op)
        add_ln2<1><<<Mq/8, 256>>>(x, tb,
                                  g1 + d*Eq, bt1 + d*Eq,
                                  g2 + d*Eq, bt2 + d*Eq, x, xh);

        // FFN1 -> fp16 h (relu), FFN2 -> fp32 tb
        mma_gemm2<1,0,1><<<dim3(FFq/256, Mq/128, 1), 256, GEMM_SMEM>>>(
            xh, W1f + (size_t)d*2048*512,
            b1 + (size_t)d*FFq, nullptr, hb, Mq, FFq, Eq, 0, 0, 0, 0);
        mma_gemm2<0,1,0><<<dim3(Eq/256, Mq/128, 1), 256, GEMM_SMEM>>>(
            hb, W2f + (size_t)d*512*2048,
            b2 + (size_t)d*Eq, tb, nullptr, Mq, Eq, FFq, 0, 0, 0, 0);

        if (d == 3)
            add_ln1<0><<<Mq/8, 256>>>(x, tb, g3 + d*Eq, bt3 + d*Eq,
                                      (float*)d_out, nullptr);
        else
            add_ln1<1><<<Mq/8, 256>>>(x, tb, g3 + d*Eq, bt3 + d*Eq, x, xh);
    }
}

// round 13
// speedup vs baseline: 1.0554x; 1.0554x over previous
#include <cuda_runtime.h>
#include <cuda_fp16.h>
#include <cuda_bf16.h>
#include <math.h>
#include <stdint.h>

// Problem constants
#define Bq   8
#define Lq   1024
#define Eq   512
#define Hq   8
#define FFq  2048
#define Mq   (Bq*Lq)          // 8192 tokens

typedef __half        fp16;
typedef __nv_bfloat16 bf16;

// ---------------- scratch (static device globals; allocation-free) ----------
__device__ float g_x [Mq*Eq];        // current activations (fp32, residual path)
__device__ float g_sv[Bq*Hq*Lq];     // per-(b,h,i) 0.125/sum(exp)
__device__ float g_t [Mq*Eq];        // sa / ff temp (fp32)
__device__ bf16  g_P [(size_t)Bq*Hq*Lq*Lq];  // per-head exp(logits), bf16, causal tiles

// fp16 buffers (plain quantized)
__device__ fp16 g_xh [Mq*Eq];
__device__ fp16 g_qk [Mq*1024];
__device__ fp16 g_aw [(size_t)Bq*Lq*Lq];
__device__ fp16 g_h  [Mq*FFq];
__device__ fp16 g_Wq [4*1024*512];
__device__ fp16 g_W1 [4*2048*512];
__device__ fp16 g_W2 [4*512*2048];

// ---------------- helpers ------------------------------------------------------
__device__ __forceinline__ float warp_sum(float s){
    #pragma unroll
    for (int o=16;o;o>>=1) s += __shfl_xor_sync(0xffffffffu, s, o);
    return s;
}
__device__ __forceinline__ uint32_t hquant(float x0, float x1){
    return (uint32_t)__half_as_ushort(__float2half_rn(x0)) |
           ((uint32_t)__half_as_ushort(__float2half_rn(x1)) << 16);
}
__device__ __forceinline__ uint32_t bpack(float x0, float x1){
    __nv_bfloat162 b = __floats2bfloat162_rn(x0, x1);
    return *(uint32_t*)&b;
}
__device__ __forceinline__ uint32_t smem_u32(const void* p){
    uint32_t a;
    asm("{ .reg .u64 t; cvta.to.shared.u64 t, %1; cvt.u32.u64 %0, t; }" : "=r"(a) : "l"(p));
    return a;
}
__device__ __forceinline__ void cp16(uint32_t dst, const void* src){
    asm volatile("cp.async.cg.shared.global [%0], [%1], 16;" :: "r"(dst), "l"(src));
}
#define CP_COMMIT() asm volatile("cp.async.commit_group;" ::: "memory")
#define CP_WAIT0()  asm volatile("cp.async.wait_group 0;" ::: "memory")
#define CP_WAIT1()  asm volatile("cp.async.wait_group 1;" ::: "memory")

#define LDSM_X4(r, addr) \
    asm volatile("ldmatrix.sync.aligned.m8n8.x4.shared.b16 {%0,%1,%2,%3}, [%4];" \
        : "=r"((r)[0]), "=r"((r)[1]), "=r"((r)[2]), "=r"((r)[3]) : "r"(addr))
#define LDSM_X4_T(r, addr) \
    asm volatile("ldmatrix.sync.aligned.m8n8.x4.trans.shared.b16 {%0,%1,%2,%3}, [%4];" \
        : "=r"((r)[0]), "=r"((r)[1]), "=r"((r)[2]), "=r"((r)[3]) : "r"(addr))

__device__ __forceinline__ void mma16816(float* c, const uint32_t* a, const uint32_t* b){
    asm volatile(
        "mma.sync.aligned.m16n8k16.row.col.f32.f16.f16.f32 "
        "{%0,%1,%2,%3}, {%4,%5,%6,%7}, {%8,%9}, {%0,%1,%2,%3};\n"
        : "+f"(c[0]), "+f"(c[1]), "+f"(c[2]), "+f"(c[3])
        : "r"(a[0]), "r"(a[1]), "r"(a[2]), "r"(a[3]), "r"(b[0]), "r"(b[1]));
}

// ============================================================================
// Quantization kernels
// ============================================================================
__global__ __launch_bounds__(256) void quant_wq(
    const float* __restrict__ Wqkv, fp16* __restrict__ Wq)
{
    const int per = 1024*512/4;
    int i = blockIdx.x*256 + threadIdx.x;
    if (i >= 4*per) return;
    int d = i / per, r = i - d*per;
    float4 v = ((const float4*)(Wqkv + (size_t)d*1536*512))[r];
    ((uint2*)(Wq + (size_t)d*1024*512))[r] =
        make_uint2(hquant(v.x, v.y), hquant(v.z, v.w));
}

__global__ __launch_bounds__(256) void quant_arr(
    const float* __restrict__ in, fp16* __restrict__ oh, int n4)
{
    int i = blockIdx.x*256 + threadIdx.x;
    if (i >= n4) return;
    float4 v = ((const float4*)in)[i];
    ((uint2*)oh)[i] = make_uint2(hquant(v.x, v.y), hquant(v.z, v.w));
}

__global__ __launch_bounds__(256) void quant_copy(
    const float* __restrict__ in, float* __restrict__ out,
    fp16* __restrict__ oh, int n4)
{
    int i = blockIdx.x*256 + threadIdx.x;
    if (i >= n4) return;
    float4 v = ((const float4*)in)[i];
    ((float4*)out)[i] = v;
    ((uint2*)oh)[i] = make_uint2(hquant(v.x, v.y), hquant(v.z, v.w));
}

// ============================================================================
// Tensor-core GEMM, fp16 x fp16, fp32 accumulate.
// Tile 128(M) x 256(N), BK=32, 256 threads (2x4 warps, 64x64 each),
// 3-stage cp.async ring, single __syncthreads per chunk, ldmatrix fragments.
// TRB=0: C = A[M,K] * B[N,K]^T   (B row-major n-by-k, non-trans ldmatrix)
// TRB=1: C = A[M,K] * B[K,N]     (B row-major k-by-n, trans ldmatrix)
// ============================================================================
#define SA_U32   2560                   // A stage: 128 rows * 20 u32
#define SB_U32   5120                   // B stage: NT 256 rows*20 u32 (TRB uses 32*132=4224 < 5120)
#define STG_U32  (SA_U32 + SB_U32)      // 7680
#define GEMM_SMEM (3 * STG_U32 * 4)     // 92160 B

template<int RELU, int WF32, int WH16, int TRB>
__global__ __launch_bounds__(256, 1) void mma_gemm2(
    const fp16* __restrict__ Ah, const fp16* __restrict__ Bh,
    const float* __restrict__ bias,
    float* __restrict__ C, fp16* __restrict__ Ch,
    int M, int N, int K, long sA, long sB, long sC, int causal)
{
    extern __shared__ uint32_t sg[];
    const int bm = blockIdx.y * 128, bn = blockIdx.x * 256;
    const fp16* Abh = Ah + (size_t)blockIdx.z * sA;
    const fp16* Bbh = Bh + (size_t)blockIdx.z * sB;

    const int t    = threadIdx.x;
    const int lane = t & 31, wid = t >> 5;
    const int wm   = wid >> 2, wn = wid & 3;
    const int gid  = lane >> 2, tig = lane & 3;
    const int fr   = t >> 1, half = t & 1;

    float acc[4][8][4];
    #pragma unroll
    for (int i=0;i<4;i++)
        #pragma unroll
        for (int j=0;j<8;j++)
            #pragma unroll
            for (int q=0;q<4;q++) acc[i][j][q] = 0.f;

    const uint32_t sbase = smem_u32(sg);
    // A cp.async fill (both variants)
    const uint32_t da = sbase + (uint32_t)(fr*80) + (uint32_t)half*32;
    const fp16* ga = Abh + (size_t)(bm+fr)*K + half*16;

    // NT B fill
    const uint32_t db0 = sbase + (uint32_t)(SA_U32*4) + (uint32_t)(fr*80) + (uint32_t)half*32;
    const uint32_t db1 = db0 + 128u*80u;
    const fp16* gb0 = Bbh + (size_t)(bn+fr)*K + half*16;
    const fp16* gb1 = Bbh + (size_t)(bn+128+fr)*K + half*16;

    // TRB B fill: 32 k-rows x 512B (+16B pad -> 528B stride); thread t: row t>>3, 64B at (t&7)*64
    const uint32_t dbt = sbase + (uint32_t)(SA_U32*4) + (uint32_t)((t>>3)*528) + (uint32_t)(t&7)*64;
    const fp16* gbt = Bbh + (size_t)(t>>3)*N + bn + (t&7)*32;

    // ldmatrix bases
    const uint32_t aB = sbase + (uint32_t)((wm*64 + (lane & 15))*80) + (uint32_t)(lane >> 4)*16;
    const uint32_t bB = sbase + (uint32_t)(SA_U32*4) +
        (uint32_t)((wn*64 + ((lane >> 4) << 3) + (lane & 7))*80) +
        (uint32_t)((lane >> 3) & 1)*16;
    const uint32_t bBt = sbase + (uint32_t)(SA_U32*4) +
        (uint32_t)((((lane >> 3) & 1)*8 + (lane & 7))*528) +
        (uint32_t)(lane >> 4)*16 + (uint32_t)wn*128;

    const int kend = causal ? (bm + 128) : K;
    const int nch  = kend >> 5;

    #define G_ISSUE(ch_) do{ \
        const uint32_t st_ = (uint32_t)((ch_) % 3) * (STG_U32*4); \
        const fp16* A0_ = ga + ((ch_) << 5); \
        cp16(da + st_, A0_);  cp16(da + st_ + 16, A0_ + 8); \
        if (TRB){ \
            const fp16* BT_ = gbt + (size_t)((ch_) << 5) * N; \
            cp16(dbt + st_,      BT_);       cp16(dbt + st_ + 16, BT_ + 8); \
            cp16(dbt + st_ + 32, BT_ + 16);  cp16(dbt + st_ + 48, BT_ + 24); \
        } else { \
            const fp16* B0_ = gb0 + ((ch_) << 5); \
            const fp16* B1_ = gb1 + ((ch_) << 5); \
            cp16(db0 + st_, B0_);  cp16(db0 + st_ + 16, B0_ + 8); \
            cp16(db1 + st_, B1_);  cp16(db1 + st_ + 16, B1_ + 8); \
        } \
        CP_COMMIT(); }while(0)

    if (nch > 0) G_ISSUE(0);
    if (nch > 1) G_ISSUE(1);

    for (int ch = 0; ch < nch; ch++){
        if (ch + 1 < nch) CP_WAIT1(); else CP_WAIT0();
        __syncthreads();                 // stage ch visible; prior compute done
        if (ch + 2 < nch) G_ISSUE(ch+2); // overwrites stage read 2 iters ago

        const uint32_t so = (uint32_t)(ch % 3) * (STG_U32*4);
        #pragma unroll
        for (int ks=0; ks<2; ks++){
            uint32_t ah[4][4], bf[4][4];
            #pragma unroll
            for (int mi=0;mi<4;mi++)
                LDSM_X4(ah[mi], aB + so + (uint32_t)mi*(16*80) + (uint32_t)ks*32);
            #pragma unroll
            for (int np=0;np<4;np++){
                if (TRB) LDSM_X4_T(bf[np], bBt + so + (uint32_t)np*32 + (uint32_t)ks*(16*528));
                else     LDSM_X4  (bf[np], bB  + so + (uint32_t)np*(16*80) + (uint32_t)ks*32);
            }
            #pragma unroll
            for (int mi=0;mi<4;mi++){
                #pragma unroll
                for (int ni=0;ni<8;ni++){
                    uint32_t bb[2] = { bf[ni>>1][(ni&1)*2], bf[ni>>1][(ni&1)*2+1] };
                    mma16816(acc[mi][ni], ah[mi], bb);
                }
            }
        }
    }
    #undef G_ISSUE

    float* Cb  = WF32 ? C  + (size_t)blockIdx.z * sC : nullptr;
    fp16*  Chb = WH16 ? Ch + (size_t)blockIdx.z * sC : nullptr;
    #pragma unroll
    for (int mi=0;mi<4;mi++){
        int row = bm + wm*64 + mi*16 + gid;
        #pragma unroll
        for (int ni=0;ni<8;ni++){
            int col = bn + wn*64 + ni*8 + tig*2;
            float2 v0 = make_float2(acc[mi][ni][0], acc[mi][ni][1]);
            float2 v1 = make_float2(acc[mi][ni][2], acc[mi][ni][3]);
            if (bias){
                float2 bb = *(const float2*)(bias + col);
                v0.x += bb.x; v0.y += bb.y; v1.x += bb.x; v1.y += bb.y;
            }
            if (RELU){
                v0.x=fmaxf(v0.x,0.f); v0.y=fmaxf(v0.y,0.f);
                v1.x=fmaxf(v1.x,0.f); v1.y=fmaxf(v1.y,0.f);
            }
            if (WF32){
                *(float2*)(Cb + (size_t)row    *N + col) = v0;
                *(float2*)(Cb + (size_t)(row+8)*N + col) = v1;
            }
            if (WH16){
                *(uint32_t*)(Chb + (size_t)row    *N + col) = hquant(v0.x, v0.y);
                *(uint32_t*)(Chb + (size_t)(row+8)*N + col) = hquant(v1.x, v1.y);
            }
        }
    }
}

// ============================================================================
// Fused attention exp kernel, fp16, 3-stage cp.async K ring, ldmatrix frags
// ============================================================================
#define ATTN_SMEM (4*4608*4)
__global__ __launch_bounds__(256) void attn_exp(
    const fp16* __restrict__ qk,
    bf16* __restrict__ P, float* __restrict__ sinv)
{
    extern __shared__ uint32_t smx[];
    uint32_t* sQh = smx;
    uint32_t* sK  = smx + 4608;
    __shared__ float sred[128];

    const int bh = blockIdx.x;
    const int ti = blockIdx.y;
    const int i0 = ti * 128;
    const int b  = bh >> 3, h = bh & 7;
    const size_t qoff = (size_t)(b*Lq)*1024 + h*64;

    const int t = threadIdx.x;
    const int lane = t & 31, wid = t >> 5;
    const int wm = wid >> 2, wn = wid & 3;
    const int gid = lane >> 2, tig = lane & 3;
    const int fr = t >> 1, half = t & 1;

    if (t < 128) sred[t] = 0.f;

    const uint32_t dk = smem_u32(sK) + fr*144 + half*64;
    const fp16* gk = qk + qoff + 512 + (size_t)fr*1024 + half*32;

    #define K_ISSUE(jt_) do{ \
        const uint32_t st_ = (uint32_t)((jt_) % 3) * 18432; \
        const fp16* g_ = gk + (size_t)(jt_)*128*1024; \
        cp16(dk + st_,      g_);       cp16(dk + st_ + 16, g_ + 8); \
        cp16(dk + st_ + 32, g_ + 16);  cp16(dk + st_ + 48, g_ + 24); \
        CP_COMMIT(); }while(0)

    K_ISSUE(0);
    K_ISSUE(1);

    // load Q tile [128 x 64]
    {
        const uint4* sh = (const uint4*)(qk + qoff + (size_t)(i0+fr)*1024 + half*32);
        uint4* dh = (uint4*)(sQh + fr*36 + half*16);
        dh[0]=sh[0]; dh[1]=sh[1]; dh[2]=sh[2]; dh[3]=sh[3];
    }

    const uint32_t qB = smem_u32(sQh) +
        (uint32_t)((wm*64 + (lane & 15))*36)*4 + (uint32_t)(lane >> 4)*16;
    const uint32_t kB = smem_u32(sK) +
        (uint32_t)((wn*32 + ((lane >> 4) << 3) + (lane & 7))*36)*4 +
        (uint32_t)((lane >> 3) & 1)*16;

    float rsum[4][2];
    #pragma unroll
    for (int mi=0;mi<4;mi++){ rsum[mi][0]=0.f; rsum[mi][1]=0.f; }

    for (int jt = 0; jt < Lq/128; jt++){
        if (jt + 1 < Lq/128) CP_WAIT1(); else CP_WAIT0();
        __syncthreads();
        if (jt + 2 < Lq/128) K_ISSUE(jt+2);

        const uint32_t so = (uint32_t)(jt % 3) * 18432;
        float acc[4][4][4];
        #pragma unroll
        for (int i=0;i<4;i++)
            #pragma unroll
            for (int j=0;j<4;j++)
                #pragma unroll
                for (int q=0;q<4;q++) acc[i][j][q] = 0.f;

        #pragma unroll
        for (int ks=0; ks<4; ks++){
            uint32_t ah[4][4], bf[2][4];
            #pragma unroll
            for (int mi=0;mi<4;mi++)
                LDSM_X4(ah[mi], qB + (uint32_t)mi*(16*144) + (uint32_t)ks*32);
            #pragma unroll
            for (int np=0;np<2;np++)
                LDSM_X4(bf[np], kB + so + (uint32_t)np*(16*144) + (uint32_t)ks*32);
            #pragma unroll
            for (int mi=0;mi<4;mi++){
                #pragma unroll
                for (int ni=0;ni<4;ni++){
                    uint32_t bb[2] = { bf[ni>>1][(ni&1)*2], bf[ni>>1][(ni&1)*2+1] };
                    mma16816(acc[mi][ni], ah[mi], bb);
                }
            }
        }

        const int j0 = jt * 128;
        const bool store = (jt <= ti);
        #pragma unroll
        for (int mi=0;mi<4;mi++){
            const int row = i0 + wm*64 + mi*16 + gid;
            #pragma unroll
            for (int ni=0;ni<4;ni++){
                float e0 = __expf(acc[mi][ni][0] * 0.125f);
                float e1 = __expf(acc[mi][ni][1] * 0.125f);
                float e2 = __expf(acc[mi][ni][2] * 0.125f);
                float e3 = __expf(acc[mi][ni][3] * 0.125f);
                rsum[mi][0] += e0 + e1;
                rsum[mi][1] += e2 + e3;
                if (store){
                    const int col = j0 + wn*32 + ni*8 + tig*2;
                    bf16* p0 = P + ((size_t)bh*Lq + row)*Lq + col;
                    *(uint32_t*)p0          = bpack(e0, e1);
                    *(uint32_t*)(p0 + 8*Lq) = bpack(e2, e3);
                }
            }
        }
    }
    #undef K_ISSUE

    #pragma unroll
    for (int mi=0;mi<4;mi++){
        float r0 = rsum[mi][0], r1 = rsum[mi][1];
        r0 += __shfl_xor_sync(0xffffffffu, r0, 1);
        r0 += __shfl_xor_sync(0xffffffffu, r0, 2);
        r1 += __shfl_xor_sync(0xffffffffu, r1, 1);
        r1 += __shfl_xor_sync(0xffffffffu, r1, 2);
        if (tig == 0){
            atomicAdd(&sred[wm*64 + mi*16 + gid    ], r0);
            atomicAdd(&sred[wm*64 + mi*16 + gid + 8], r1);
        }
    }
    __syncthreads();
    if (t < 128)
        sinv[(size_t)bh*Lq + i0 + t] = 0.125f / sred[t];
}

// ============================================================================
// Fused head-average + second softmax -> fp16 W
// ============================================================================
__global__ __launch_bounds__(256) void make_w2(
    const bf16* __restrict__ P, const float* __restrict__ sinv,
    fp16* __restrict__ Wh)
{
    const int row = blockIdx.x;            // b*1024 + i
    const int b = row >> 10, i = row & 1023;
    const int t = threadIdx.x;
    __shared__ float sv8[8];
    if (t < 8) sv8[t] = sinv[(size_t)(b*8 + t)*Lq + i];
    __syncthreads();

    const int j0 = t*4;
    float v[4] = {0.f,0.f,0.f,0.f};
    float s = 0.f;
    if (j0 <= i){
        float a[4] = {0.f,0.f,0.f,0.f};
        const bf16* pb = P + ((size_t)(b*8)*Lq + i)*Lq + j0;
        #pragma unroll
        for (int h=0; h<8; h++){
            const uint2 pv = *(const uint2*)(pb + (size_t)h*Lq*Lq);
            const float sc = sv8[h];
            float2 f0 = __bfloat1622float2(*(const __nv_bfloat162*)&pv.x);
            float2 f1 = __bfloat1622float2(*(const __nv_bfloat162*)&pv.y);
            a[0] = fmaf(f0.x, sc, a[0]); a[1] = fmaf(f0.y, sc, a[1]);
            a[2] = fmaf(f1.x, sc, a[2]); a[3] = fmaf(f1.y, sc, a[3]);
        }
        #pragma unroll
        for (int u=0;u<4;u++){
            int j = j0 + u;
            if (j <= i){
                float pos = __expf((float)(j - i) * 0.1f);
                v[u] = __expf(a[u] + pos);
                s += v[u];
            }
        }
    }
    s = warp_sum(s);
    __shared__ float red[8];
    if ((t & 31) == 0) red[t >> 5] = s;
    __syncthreads();
    float tot = 0.f;
    #pragma unroll
    for (int w=0;w<8;w++) tot += red[w];
    float inv = 1.f / tot;
    *(uint2*)(Wh + (size_t)row*Lq + j0) =
        make_uint2(hquant(v[0]*inv, v[1]*inv), hquant(v[2]*inv, v[3]*inv));
}

// ============================================================================
// LayerNorm kernels (one warp per 512-wide row); optional fp16 output
// ============================================================================
template<int WH>
__global__ __launch_bounds__(256) void add_ln2(
    const float* __restrict__ x, const float* __restrict__ y,
    const float* __restrict__ g1, const float* __restrict__ b1,
    const float* __restrict__ g2, const float* __restrict__ b2,
    float* __restrict__ out, fp16* __restrict__ oh)
{
    const int row  = blockIdx.x * 8 + (threadIdx.x >> 5);
    const int lane = threadIdx.x & 31;
    const float* xr = x + (size_t)row * Eq;
    const float* yr = y + (size_t)row * Eq;
    float v[16]; float s = 0.f;
    #pragma unroll
    for (int u=0;u<16;u++){ int c = lane + u*32; v[u] = xr[c] + yr[c]; s += v[u]; }
    s = warp_sum(s);
    float mean = s * (1.0f/Eq);
    float sq = 0.f;
    #pragma unroll
    for (int u=0;u<16;u++){ float d = v[u]-mean; sq += d*d; }
    sq = warp_sum(sq);
    float rstd = rsqrtf(sq*(1.0f/Eq) + 1e-5f);
    float s2 = 0.f;
    #pragma unroll
    for (int u=0;u<16;u++){ int c = lane + u*32; v[u] = (v[u]-mean)*rstd*g1[c] + b1[c]; s2 += v[u]; }
    s2 = warp_sum(s2);
    float m2 = s2 * (1.0f/Eq);
    float q2 = 0.f;
    #pragma unroll
    for (int u=0;u<16;u++){ float d = v[u]-m2; q2 += d*d; }
    q2 = warp_sum(q2);
    float r2 = rsqrtf(q2*(1.0f/Eq) + 1e-5f);
    float* orow = out + (size_t)row * Eq;
    #pragma unroll
    for (int u=0;u<16;u++){
        int c = lane + u*32;
        float o = (v[u]-m2)*r2*g2[c] + b2[c];
        orow[c] = o;
        if (WH) oh[(size_t)row*Eq + c] = __float2half_rn(o);
    }
}

template<int WH>
__global__ __launch_bounds__(256) void add_ln1(
    const float* __restrict__ x, const float* __restrict__ y,
    const float* __restrict__ g, const float* __restrict__ b,
    float* __restrict__ out, fp16* __restrict__ oh)
{
    const int row  = blockIdx.x * 8 + (threadIdx.x >> 5);
    const int lane = threadIdx.x & 31;
    const float* xr = x + (size_t)row * Eq;
    const float* yr = y + (size_t)row * Eq;
    float v[16]; float s = 0.f;
    #pragma unroll
    for (int u=0;u<16;u++){ int c = lane + u*32; v[u] = xr[c] + yr[c]; s += v[u]; }
    s = warp_sum(s);
    float mean = s * (1.0f/Eq);
    float sq = 0.f;
    #pragma unroll
    for (int u=0;u<16;u++){ float d = v[u]-mean; sq += d*d; }
    sq = warp_sum(sq);
    float rstd = rsqrtf(sq*(1.0f/Eq) + 1e-5f);
    float* orow = out + (size_t)row * Eq;
    #pragma unroll
    for (int u=0;u<16;u++){
        int c = lane + u*32;
        float o = (v[u]-mean)*rstd*g[c] + b[c];
        orow[c] = o;
        if (WH) oh[(size_t)row*Eq + c] = __float2half_rn(o);
    }
}

// ============================================================================
// Launch
// ============================================================================
extern "C" void kernel_launch(void* const* d_in, const int* in_sizes, int n_in,
                              void* d_out, int out_size)
{
    const float* input = (const float*)d_in[0];
    const float* Wqkv  = (const float*)d_in[1];
    const float* bqkv  = (const float*)d_in[2];
    const float* W1    = (const float*)d_in[3];
    const float* b1    = (const float*)d_in[4];
    const float* W2    = (const float*)d_in[5];
    const float* b2    = (const float*)d_in[6];
    const float* g1    = (const float*)d_in[7];
    const float* bt1   = (const float*)d_in[8];
    const float* g2    = (const float*)d_in[9];
    const float* bt2   = (const float*)d_in[10];
    const float* g3    = (const float*)d_in[11];
    const float* bt3   = (const float*)d_in[12];

    float *x, *sv, *tb;
    bf16 *P;
    fp16 *xh,*qk,*aw,*hb,*Wq,*W1f,*W2f;
    cudaGetSymbolAddress((void**)&x,  g_x);
    cudaGetSymbolAddress((void**)&sv, g_sv);
    cudaGetSymbolAddress((void**)&tb, g_t);
    cudaGetSymbolAddress((void**)&P,  g_P);
    cudaGetSymbolAddress((void**)&xh, g_xh);
    cudaGetSymbolAddress((void**)&qk, g_qk);
    cudaGetSymbolAddress((void**)&aw, g_aw);
    cudaGetSymbolAddress((void**)&hb, g_h);
    cudaGetSymbolAddress((void**)&Wq, g_Wq);
    cudaGetSymbolAddress((void**)&W1f,g_W1);
    cudaGetSymbolAddress((void**)&W2f,g_W2);

    cudaFuncSetAttribute(attn_exp, cudaFuncAttributeMaxDynamicSharedMemorySize, ATTN_SMEM);
    cudaFuncSetAttribute(mma_gemm2<0,0,1,0>, cudaFuncAttributeMaxDynamicSharedMemorySize, GEMM_SMEM);
    cudaFuncSetAttribute(mma_gemm2<0,1,0,0>, cudaFuncAttributeMaxDynamicSharedMemorySize, GEMM_SMEM);
    cudaFuncSetAttribute(mma_gemm2<1,0,1,0>, cudaFuncAttributeMaxDynamicSharedMemorySize, GEMM_SMEM);
    cudaFuncSetAttribute(mma_gemm2<0,1,0,1>, cudaFuncAttributeMaxDynamicSharedMemorySize, GEMM_SMEM);

    // one-time weight quantization + input copy/quant
    {
        int n = 4*1024*512/4;
        quant_wq<<<(n+255)/256, 256>>>(Wqkv, Wq);
        int n4 = 4*2048*512/4;
        quant_arr<<<(n4+255)/256, 256>>>(W1, W1f, n4);
        quant_arr<<<(n4+255)/256, 256>>>(W2, W2f, n4);
        int nx = Mq*Eq/4;
        quant_copy<<<(nx+255)/256, 256>>>(input, x, xh, nx);
    }

    for (int d = 0; d < 4; d++){
        const float* bq = bqkv + (size_t)d * 1536;

        // q|k projection -> fp16 qk (v/out-proj of Wqkv are dead in the reference)
        mma_gemm2<0,0,1,0><<<dim3(1024/256, Mq/128, 1), 256, GEMM_SMEM>>>(
            xh, Wq + (size_t)d*1024*512,
            bq, nullptr, qk, Mq, 1024, 512, 0, 0, 0, 0);

        // fused logits+exp (stores causal bf16 P, computes sinv)
        attn_exp<<<dim3(Bq*Hq, Lq/128), 256, ATTN_SMEM>>>(qk, P, sv);

        // fused head-average + second softmax -> fp16 attention weights
        make_w2<<<Bq*Lq, 256>>>(P, sv, aw);

        // sa = W @ x: NN GEMM reading row-major xh via trans-ldmatrix (causal cutoff)
        mma_gemm2<0,1,0,1><<<dim3(Eq/256, Lq/128, Bq), 256, GEMM_SMEM>>>(
            aw, xh, nullptr, tb, nullptr,
            Lq, Eq, Lq, (long)Lq*Lq, (long)Lq*Eq, (long)Lq*Eq, 1);

        // x = LN2(LN1(x + sa))  (cross-attn block is a double-LN no-op)
        add_ln2<1><<<Mq/8, 256>>>(x, tb,
                                  g1 + d*Eq, bt1 + d*Eq,
                                  g2 + d*Eq, bt2 + d*Eq, x, xh);

        // FFN1 -> fp16 h (relu), FFN2 -> fp32 tb
        mma_gemm2<1,0,1,0><<<dim3(FFq/256, Mq/128, 1), 256, GEMM_SMEM>>>(
            xh, W1f + (size_t)d*2048*512,
            b1 + (size_t)d*FFq, nullptr, hb, Mq, FFq, Eq, 0, 0, 0, 0);
        mma_gemm2<0,1,0,0><<<dim3(Eq/256, Mq/128, 1), 256, GEMM_SMEM>>>(
            hb, W2f + (size_t)d*512*2048,
            b2 + (size_t)d*Eq, tb, nullptr, Mq, Eq, FFq, 0, 0, 0, 0);

        if (d == 3)
            add_ln1<0><<<Mq/8, 256>>>(x, tb, g3 + d*Eq, bt3 + d*Eq,
                                      (float*)d_out, nullptr);
        else
            add_ln1<1><<<Mq/8, 256>>>(x, tb, g3 + d*Eq, bt3 + d*Eq, x, xh);
    }
}

// round 14
// speedup vs baseline: 1.0556x; 1.0001x over previous
#include <cuda_runtime.h>
#include <cuda_fp16.h>
#include <cuda_bf16.h>
#include <math.h>
#include <stdint.h>

// Problem constants
#define Bq   8
#define Lq   1024
#define Eq   512
#define Hq   8
#define FFq  2048
#define Mq   (Bq*Lq)          // 8192 tokens

typedef __half        fp16;
typedef __nv_bfloat16 bf16;

// ---------------- scratch (static device globals; allocation-free) ----------
__device__ float g_x [Mq*Eq];        // current activations (fp32, residual path)
__device__ float g_sv[Bq*Hq*Lq];     // per-(b,h,i) 0.125/sum(exp)
__device__ float g_t [Mq*Eq];        // x + (sa|ffn) pre-LN sum (fp32)
__device__ bf16  g_P [(size_t)Bq*Hq*Lq*Lq];  // per-head exp(logits), bf16, causal tiles

// fp16 buffers (plain quantized)
__device__ fp16 g_xh [Mq*Eq];
__device__ fp16 g_qk [Mq*1024];
__device__ fp16 g_aw [(size_t)Bq*Lq*Lq];
__device__ fp16 g_h  [Mq*FFq];
__device__ fp16 g_Wq [4*1024*512];
__device__ fp16 g_W1 [4*2048*512];
__device__ fp16 g_W2 [4*512*2048];

// ---------------- helpers ------------------------------------------------------
__device__ __forceinline__ float warp_sum(float s){
    #pragma unroll
    for (int o=16;o;o>>=1) s += __shfl_xor_sync(0xffffffffu, s, o);
    return s;
}
__device__ __forceinline__ uint32_t hquant(float x0, float x1){
    return (uint32_t)__half_as_ushort(__float2half_rn(x0)) |
           ((uint32_t)__half_as_ushort(__float2half_rn(x1)) << 16);
}
__device__ __forceinline__ uint32_t bpack(float x0, float x1){
    __nv_bfloat162 b = __floats2bfloat162_rn(x0, x1);
    return *(uint32_t*)&b;
}
__device__ __forceinline__ uint32_t smem_u32(const void* p){
    uint32_t a;
    asm("{ .reg .u64 t; cvta.to.shared.u64 t, %1; cvt.u32.u64 %0, t; }" : "=r"(a) : "l"(p));
    return a;
}
__device__ __forceinline__ void cp16(uint32_t dst, const void* src){
    asm volatile("cp.async.cg.shared.global [%0], [%1], 16;" :: "r"(dst), "l"(src));
}
#define CP_COMMIT() asm volatile("cp.async.commit_group;" ::: "memory")
#define CP_WAIT0()  asm volatile("cp.async.wait_group 0;" ::: "memory")
#define CP_WAIT1()  asm volatile("cp.async.wait_group 1;" ::: "memory")

#define LDSM_X4(r, addr) \
    asm volatile("ldmatrix.sync.aligned.m8n8.x4.shared.b16 {%0,%1,%2,%3}, [%4];" \
        : "=r"((r)[0]), "=r"((r)[1]), "=r"((r)[2]), "=r"((r)[3]) : "r"(addr))
#define LDSM_X4_T(r, addr) \
    asm volatile("ldmatrix.sync.aligned.m8n8.x4.trans.shared.b16 {%0,%1,%2,%3}, [%4];" \
        : "=r"((r)[0]), "=r"((r)[1]), "=r"((r)[2]), "=r"((r)[3]) : "r"(addr))

__device__ __forceinline__ void mma16816(float* c, const uint32_t* a, const uint32_t* b){
    asm volatile(
        "mma.sync.aligned.m16n8k16.row.col.f32.f16.f16.f32 "
        "{%0,%1,%2,%3}, {%4,%5,%6,%7}, {%8,%9}, {%0,%1,%2,%3};\n"
        : "+f"(c[0]), "+f"(c[1]), "+f"(c[2]), "+f"(c[3])
        : "r"(a[0]), "r"(a[1]), "r"(a[2]), "r"(a[3]), "r"(b[0]), "r"(b[1]));
}

// ============================================================================
// Merged one-time quantization: Wqkv(q|k slices), W1, W2, input copy+quant
// ============================================================================
__global__ __launch_bounds__(256) void quant_all(
    const float* __restrict__ Wqkv, const float* __restrict__ W1,
    const float* __restrict__ W2,   const float* __restrict__ input,
    fp16* __restrict__ Wq, fp16* __restrict__ W1f, fp16* __restrict__ W2f,
    float* __restrict__ x, fp16* __restrict__ xh)
{
    const int nWq = 4*1024*512/4;   // 524288
    const int nW  = 4*2048*512/4;   // 1048576
    const int nx  = Mq*Eq/4;        // 1048576
    int i = blockIdx.x*256 + threadIdx.x;
    if (i < nWq){
        const int per = 1024*512/4;
        int d = i / per, r = i - d*per;
        float4 v = ((const float4*)(Wqkv + (size_t)d*1536*512))[r];
        ((uint2*)(Wq + (size_t)d*1024*512))[r] =
            make_uint2(hquant(v.x, v.y), hquant(v.z, v.w));
        return;
    }
    i -= nWq;
    if (i < nW){
        float4 v = ((const float4*)W1)[i];
        ((uint2*)W1f)[i] = make_uint2(hquant(v.x, v.y), hquant(v.z, v.w));
        return;
    }
    i -= nW;
    if (i < nW){
        float4 v = ((const float4*)W2)[i];
        ((uint2*)W2f)[i] = make_uint2(hquant(v.x, v.y), hquant(v.z, v.w));
        return;
    }
    i -= nW;
    if (i < nx){
        float4 v = ((const float4*)input)[i];
        ((float4*)x)[i] = v;
        ((uint2*)xh)[i] = make_uint2(hquant(v.x, v.y), hquant(v.z, v.w));
    }
}
#define QUANT_TOTAL (4*1024*512/4 + 2*(4*2048*512/4) + Mq*Eq/4)

// ============================================================================
// Tensor-core GEMM, fp16 x fp16, fp32 accumulate.
// Tile 128(M) x 256(N), BK=32, 256 threads (2x4 warps, 64x64 each),
// 3-stage cp.async ring, single __syncthreads per chunk, ldmatrix fragments.
// TRB=0: C = A[M,K] * B[N,K]^T ; TRB=1: C = A[M,K] * B[K,N] (trans ldmatrix)
// ADDR=1: C += Rres (fp32 residual at C layout) fused in epilogue.
// ============================================================================
#define SA_U32   2560                   // A stage: 128 rows * 20 u32
#define SB_U32   5120                   // B stage: NT 256 rows*20 u32 (TRB uses 32*132 u32 < 5120)
#define STG_U32  (SA_U32 + SB_U32)      // 7680
#define GEMM_SMEM (3 * STG_U32 * 4)     // 92160 B

template<int RELU, int WF32, int WH16, int TRB, int ADDR>
__global__ __launch_bounds__(256, 1) void mma_gemm2(
    const fp16* __restrict__ Ah, const fp16* __restrict__ Bh,
    const float* __restrict__ bias, const float* __restrict__ Rres,
    float* __restrict__ C, fp16* __restrict__ Ch,
    int M, int N, int K, long sA, long sB, long sC, int causal)
{
    extern __shared__ uint32_t sg[];
    const int bm = blockIdx.y * 128, bn = blockIdx.x * 256;
    const fp16* Abh = Ah + (size_t)blockIdx.z * sA;
    const fp16* Bbh = Bh + (size_t)blockIdx.z * sB;

    const int t    = threadIdx.x;
    const int lane = t & 31, wid = t >> 5;
    const int wm   = wid >> 2, wn = wid & 3;
    const int gid  = lane >> 2, tig = lane & 3;
    const int fr   = t >> 1, half = t & 1;

    float acc[4][8][4];
    #pragma unroll
    for (int i=0;i<4;i++)
        #pragma unroll
        for (int j=0;j<8;j++)
            #pragma unroll
            for (int q=0;q<4;q++) acc[i][j][q] = 0.f;

    const uint32_t sbase = smem_u32(sg);
    const uint32_t da = sbase + (uint32_t)(fr*80) + (uint32_t)half*32;
    const fp16* ga = Abh + (size_t)(bm+fr)*K + half*16;

    // NT B fill
    const uint32_t db0 = sbase + (uint32_t)(SA_U32*4) + (uint32_t)(fr*80) + (uint32_t)half*32;
    const uint32_t db1 = db0 + 128u*80u;
    const fp16* gb0 = Bbh + (size_t)(bn+fr)*K + half*16;
    const fp16* gb1 = Bbh + (size_t)(bn+128+fr)*K + half*16;

    // TRB B fill: 32 k-rows x 512B (+16B pad -> 528B stride)
    const uint32_t dbt = sbase + (uint32_t)(SA_U32*4) + (uint32_t)((t>>3)*528) + (uint32_t)(t&7)*64;
    const fp16* gbt = Bbh + (size_t)(t>>3)*N + bn + (t&7)*32;

    // ldmatrix bases
    const uint32_t aB = sbase + (uint32_t)((wm*64 + (lane & 15))*80) + (uint32_t)(lane >> 4)*16;
    const uint32_t bB = sbase + (uint32_t)(SA_U32*4) +
        (uint32_t)((wn*64 + ((lane >> 4) << 3) + (lane & 7))*80) +
        (uint32_t)((lane >> 3) & 1)*16;
    const uint32_t bBt = sbase + (uint32_t)(SA_U32*4) +
        (uint32_t)((((lane >> 3) & 1)*8 + (lane & 7))*528) +
        (uint32_t)(lane >> 4)*16 + (uint32_t)wn*128;

    const int kend = causal ? (bm + 128) : K;
    const int nch  = kend >> 5;

    #define G_ISSUE(ch_) do{ \
        const uint32_t st_ = (uint32_t)((ch_) % 3) * (STG_U32*4); \
        const fp16* A0_ = ga + ((ch_) << 5); \
        cp16(da + st_, A0_);  cp16(da + st_ + 16, A0_ + 8); \
        if (TRB){ \
            const fp16* BT_ = gbt + (size_t)((ch_) << 5) * N; \
            cp16(dbt + st_,      BT_);       cp16(dbt + st_ + 16, BT_ + 8); \
            cp16(dbt + st_ + 32, BT_ + 16);  cp16(dbt + st_ + 48, BT_ + 24); \
        } else { \
            const fp16* B0_ = gb0 + ((ch_) << 5); \
            const fp16* B1_ = gb1 + ((ch_) << 5); \
            cp16(db0 + st_, B0_);  cp16(db0 + st_ + 16, B0_ + 8); \
            cp16(db1 + st_, B1_);  cp16(db1 + st_ + 16, B1_ + 8); \
        } \
        CP_COMMIT(); }while(0)

    if (nch > 0) G_ISSUE(0);
    if (nch > 1) G_ISSUE(1);

    for (int ch = 0; ch < nch; ch++){
        if (ch + 1 < nch) CP_WAIT1(); else CP_WAIT0();
        __syncthreads();                 // stage ch visible; prior compute done
        if (ch + 2 < nch) G_ISSUE(ch+2); // overwrites stage read 2 iters ago

        const uint32_t so = (uint32_t)(ch % 3) * (STG_U32*4);
        #pragma unroll
        for (int ks=0; ks<2; ks++){
            uint32_t ah[4][4], bf[4][4];
            #pragma unroll
            for (int mi=0;mi<4;mi++)
                LDSM_X4(ah[mi], aB + so + (uint32_t)mi*(16*80) + (uint32_t)ks*32);
            #pragma unroll
            for (int np=0;np<4;np++){
                if (TRB) LDSM_X4_T(bf[np], bBt + so + (uint32_t)np*32 + (uint32_t)ks*(16*528));
                else     LDSM_X4  (bf[np], bB  + so + (uint32_t)np*(16*80) + (uint32_t)ks*32);
            }
            #pragma unroll
            for (int mi=0;mi<4;mi++){
                #pragma unroll
                for (int ni=0;ni<8;ni++){
                    uint32_t bb[2] = { bf[ni>>1][(ni&1)*2], bf[ni>>1][(ni&1)*2+1] };
                    mma16816(acc[mi][ni], ah[mi], bb);
                }
            }
        }
    }
    #undef G_ISSUE

    float*       Cb  = WF32 ? C    + (size_t)blockIdx.z * sC : nullptr;
    fp16*        Chb = WH16 ? Ch   + (size_t)blockIdx.z * sC : nullptr;
    const float* Rb  = ADDR ? Rres + (size_t)blockIdx.z * sC : nullptr;
    #pragma unroll
    for (int mi=0;mi<4;mi++){
        int row = bm + wm*64 + mi*16 + gid;
        #pragma unroll
        for (int ni=0;ni<8;ni++){
            int col = bn + wn*64 + ni*8 + tig*2;
            float2 v0 = make_float2(acc[mi][ni][0], acc[mi][ni][1]);
            float2 v1 = make_float2(acc[mi][ni][2], acc[mi][ni][3]);
            if (bias){
                float2 bb = *(const float2*)(bias + col);
                v0.x += bb.x; v0.y += bb.y; v1.x += bb.x; v1.y += bb.y;
            }
            if (RELU){
                v0.x=fmaxf(v0.x,0.f); v0.y=fmaxf(v0.y,0.f);
                v1.x=fmaxf(v1.x,0.f); v1.y=fmaxf(v1.y,0.f);
            }
            if (ADDR){
                float2 r0 = *(const float2*)(Rb + (size_t)row    *N + col);
                float2 r1 = *(const float2*)(Rb + (size_t)(row+8)*N + col);
                v0.x += r0.x; v0.y += r0.y; v1.x += r1.x; v1.y += r1.y;
            }
            if (WF32){
                *(float2*)(Cb + (size_t)row    *N + col) = v0;
                *(float2*)(Cb + (size_t)(row+8)*N + col) = v1;
            }
            if (WH16){
                *(uint32_t*)(Chb + (size_t)row    *N + col) = hquant(v0.x, v0.y);
                *(uint32_t*)(Chb + (size_t)(row+8)*N + col) = hquant(v1.x, v1.y);
            }
        }
    }
}

// ============================================================================
// Fused attention exp kernel, fp16, 3-stage cp.async K ring, ldmatrix frags
// ============================================================================
#define ATTN_SMEM (4*4608*4)
__global__ __launch_bounds__(256) void attn_exp(
    const fp16* __restrict__ qk,
    bf16* __restrict__ P, float* __restrict__ sinv)
{
    extern __shared__ uint32_t smx[];
    uint32_t* sQh = smx;
    uint32_t* sK  = smx + 4608;
    __shared__ float sred[128];

    const int bh = blockIdx.x;
    const int ti = blockIdx.y;
    const int i0 = ti * 128;
    const int b  = bh >> 3, h = bh & 7;
    const size_t qoff = (size_t)(b*Lq)*1024 + h*64;

    const int t = threadIdx.x;
    const int lane = t & 31, wid = t >> 5;
    const int wm = wid >> 2, wn = wid & 3;
    const int gid = lane >> 2, tig = lane & 3;
    const int fr = t >> 1, half = t & 1;

    if (t < 128) sred[t] = 0.f;

    const uint32_t dk = smem_u32(sK) + fr*144 + half*64;
    const fp16* gk = qk + qoff + 512 + (size_t)fr*1024 + half*32;

    #define K_ISSUE(jt_) do{ \
        const uint32_t st_ = (uint32_t)((jt_) % 3) * 18432; \
        const fp16* g_ = gk + (size_t)(jt_)*128*1024; \
        cp16(dk + st_,      g_);       cp16(dk + st_ + 16, g_ + 8); \
        cp16(dk + st_ + 32, g_ + 16);  cp16(dk + st_ + 48, g_ + 24); \
        CP_COMMIT(); }while(0)

    K_ISSUE(0);
    K_ISSUE(1);

    // load Q tile [128 x 64]
    {
        const uint4* sh = (const uint4*)(qk + qoff + (size_t)(i0+fr)*1024 + half*32);
        uint4* dh = (uint4*)(sQh + fr*36 + half*16);
        dh[0]=sh[0]; dh[1]=sh[1]; dh[2]=sh[2]; dh[3]=sh[3];
    }

    const uint32_t qB = smem_u32(sQh) +
        (uint32_t)((wm*64 + (lane & 15))*36)*4 + (uint32_t)(lane >> 4)*16;
    const uint32_t kB = smem_u32(sK) +
        (uint32_t)((wn*32 + ((lane >> 4) << 3) + (lane & 7))*36)*4 +
        (uint32_t)((lane >> 3) & 1)*16;

    float rsum[4][2];
    #pragma unroll
    for (int mi=0;mi<4;mi++){ rsum[mi][0]=0.f; rsum[mi][1]=0.f; }

    for (int jt = 0; jt < Lq/128; jt++){
        if (jt + 1 < Lq/128) CP_WAIT1(); else CP_WAIT0();
        __syncthreads();
        if (jt + 2 < Lq/128) K_ISSUE(jt+2);

        const uint32_t so = (uint32_t)(jt % 3) * 18432;
        float acc[4][4][4];
        #pragma unroll
        for (int i=0;i<4;i++)
            #pragma unroll
            for (int j=0;j<4;j++)
                #pragma unroll
                for (int q=0;q<4;q++) acc[i][j][q] = 0.f;

        #pragma unroll
        for (int ks=0; ks<4; ks++){
            uint32_t ah[4][4], bf[2][4];
            #pragma unroll
            for (int mi=0;mi<4;mi++)
                LDSM_X4(ah[mi], qB + (uint32_t)mi*(16*144) + (uint32_t)ks*32);
            #pragma unroll
            for (int np=0;np<2;np++)
                LDSM_X4(bf[np], kB + so + (uint32_t)np*(16*144) + (uint32_t)ks*32);
            #pragma unroll
            for (int mi=0;mi<4;mi++){
                #pragma unroll
                for (int ni=0;ni<4;ni++){
                    uint32_t bb[2] = { bf[ni>>1][(ni&1)*2], bf[ni>>1][(ni&1)*2+1] };
                    mma16816(acc[mi][ni], ah[mi], bb);
                }
            }
        }

        const int j0 = jt * 128;
        const bool store = (jt <= ti);
        #pragma unroll
        for (int mi=0;mi<4;mi++){
            const int row = i0 + wm*64 + mi*16 + gid;
            #pragma unroll
            for (int ni=0;ni<4;ni++){
                float e0 = __expf(acc[mi][ni][0] * 0.125f);
                float e1 = __expf(acc[mi][ni][1] * 0.125f);
                float e2 = __expf(acc[mi][ni][2] * 0.125f);
                float e3 = __expf(acc[mi][ni][3] * 0.125f);
                rsum[mi][0] += e0 + e1;
                rsum[mi][1] += e2 + e3;
                if (store){
                    const int col = j0 + wn*32 + ni*8 + tig*2;
                    bf16* p0 = P + ((size_t)bh*Lq + row)*Lq + col;
                    *(uint32_t*)p0          = bpack(e0, e1);
                    *(uint32_t*)(p0 + 8*Lq) = bpack(e2, e3);
                }
            }
        }
    }
    #undef K_ISSUE

    #pragma unroll
    for (int mi=0;mi<4;mi++){
        float r0 = rsum[mi][0], r1 = rsum[mi][1];
        r0 += __shfl_xor_sync(0xffffffffu, r0, 1);
        r0 += __shfl_xor_sync(0xffffffffu, r0, 2);
        r1 += __shfl_xor_sync(0xffffffffu, r1, 1);
        r1 += __shfl_xor_sync(0xffffffffu, r1, 2);
        if (tig == 0){
            atomicAdd(&sred[wm*64 + mi*16 + gid    ], r0);
            atomicAdd(&sred[wm*64 + mi*16 + gid + 8], r1);
        }
    }
    __syncthreads();
    if (t < 128)
        sinv[(size_t)bh*Lq + i0 + t] = 0.125f / sred[t];
}

// ============================================================================
// Fused head-average + second softmax -> fp16 W
// ============================================================================
__global__ __launch_bounds__(256) void make_w2(
    const bf16* __restrict__ P, const float* __restrict__ sinv,
    fp16* __restrict__ Wh)
{
    const int row = blockIdx.x;            // b*1024 + i
    const int b = row >> 10, i = row & 1023;
    const int t = threadIdx.x;
    __shared__ float sv8[8];
    if (t < 8) sv8[t] = sinv[(size_t)(b*8 + t)*Lq + i];
    __syncthreads();

    const int j0 = t*4;
    float v[4] = {0.f,0.f,0.f,0.f};
    float s = 0.f;
    if (j0 <= i){
        float a[4] = {0.f,0.f,0.f,0.f};
        const bf16* pb = P + ((size_t)(b*8)*Lq + i)*Lq + j0;
        #pragma unroll
        for (int h=0; h<8; h++){
            const uint2 pv = *(const uint2*)(pb + (size_t)h*Lq*Lq);
            const float sc = sv8[h];
            float2 f0 = __bfloat1622float2(*(const __nv_bfloat162*)&pv.x);
            float2 f1 = __bfloat1622float2(*(const __nv_bfloat162*)&pv.y);
            a[0] = fmaf(f0.x, sc, a[0]); a[1] = fmaf(f0.y, sc, a[1]);
            a[2] = fmaf(f1.x, sc, a[2]); a[3] = fmaf(f1.y, sc, a[3]);
        }
        #pragma unroll
        for (int u=0;u<4;u++){
            int j = j0 + u;
            if (j <= i){
                float pos = __expf((float)(j - i) * 0.1f);
                v[u] = __expf(a[u] + pos);
                s += v[u];
            }
        }
    }
    s = warp_sum(s);
    __shared__ float red[8];
    if ((t & 31) == 0) red[t >> 5] = s;
    __syncthreads();
    float tot = 0.f;
    #pragma unroll
    for (int w=0;w<8;w++) tot += red[w];
    float inv = 1.f / tot;
    *(uint2*)(Wh + (size_t)row*Lq + j0) =
        make_uint2(hquant(v[0]*inv, v[1]*inv), hquant(v[2]*inv, v[3]*inv));
}

// ============================================================================
// LayerNorm kernels (one warp per 512-wide row); single pre-summed input z.
// ============================================================================
template<int WH>
__global__ __launch_bounds__(256) void ln2(
    const float* __restrict__ z,
    const float* __restrict__ g1, const float* __restrict__ b1,
    const float* __restrict__ g2, const float* __restrict__ b2,
    float* __restrict__ out, fp16* __restrict__ oh)
{
    const int row  = blockIdx.x * 8 + (threadIdx.x >> 5);
    const int lane = threadIdx.x & 31;
    const float* zr = z + (size_t)row * Eq;
    float v[16]; float s = 0.f;
    #pragma unroll
    for (int u=0;u<16;u++){ int c = lane + u*32; v[u] = zr[c]; s += v[u]; }
    s = warp_sum(s);
    float mean = s * (1.0f/Eq);
    float sq = 0.f;
    #pragma unroll
    for (int u=0;u<16;u++){ float d = v[u]-mean; sq += d*d; }
    sq = warp_sum(sq);
    float rstd = rsqrtf(sq*(1.0f/Eq) + 1e-5f);
    float s2 = 0.f;
    #pragma unroll
    for (int u=0;u<16;u++){ int c = lane + u*32; v[u] = (v[u]-mean)*rstd*g1[c] + b1[c]; s2 += v[u]; }
    s2 = warp_sum(s2);
    float m2 = s2 * (1.0f/Eq);
    float q2 = 0.f;
    #pragma unroll
    for (int u=0;u<16;u++){ float d = v[u]-m2; q2 += d*d; }
    q2 = warp_sum(q2);
    float r2 = rsqrtf(q2*(1.0f/Eq) + 1e-5f);
    float* orow = out + (size_t)row * Eq;
    #pragma unroll
    for (int u=0;u<16;u++){
        int c = lane + u*32;
        float o = (v[u]-m2)*r2*g2[c] + b2[c];
        orow[c] = o;
        if (WH) oh[(size_t)row*Eq + c] = __float2half_rn(o);
    }
}

template<int WH>
__global__ __launch_bounds__(256) void ln1(
    const float* __restrict__ z,
    const float* __restrict__ g, const float* __restrict__ b,
    float* __restrict__ out, fp16* __restrict__ oh)
{
    const int row  = blockIdx.x * 8 + (threadIdx.x >> 5);
    const int lane = threadIdx.x & 31;
    const float* zr = z + (size_t)row * Eq;
    float v[16]; float s = 0.f;
    #pragma unroll
    for (int u=0;u<16;u++){ int c = lane + u*32; v[u] = zr[c]; s += v[u]; }
    s = warp_sum(s);
    float mean = s * (1.0f/Eq);
    float sq = 0.f;
    #pragma unroll
    for (int u=0;u<16;u++){ float d = v[u]-mean; sq += d*d; }
    sq = warp_sum(sq);
    float rstd = rsqrtf(sq*(1.0f/Eq) + 1e-5f);
    float* orow = out + (size_t)row * Eq;
    #pragma unroll
    for (int u=0;u<16;u++){
        int c = lane + u*32;
        float o = (v[u]-mean)*rstd*g[c] + b[c];
        orow[c] = o;
        if (WH) oh[(size_t)row*Eq + c] = __float2half_rn(o);
    }
}

// ============================================================================
// Launch
// ============================================================================
extern "C" void kernel_launch(void* const* d_in, const int* in_sizes, int n_in,
                              void* d_out, int out_size)
{
    const float* input = (const float*)d_in[0];
    const float* Wqkv  = (const float*)d_in[1];
    const float* bqkv  = (const float*)d_in[2];
    const float* W1    = (const float*)d_in[3];
    const float* b1    = (const float*)d_in[4];
    const float* W2    = (const float*)d_in[5];
    const float* b2    = (const float*)d_in[6];
    const float* g1    = (const float*)d_in[7];
    const float* bt1   = (const float*)d_in[8];
    const float* g2    = (const float*)d_in[9];
    const float* bt2   = (const float*)d_in[10];
    const float* g3    = (const float*)d_in[11];
    const float* bt3   = (const float*)d_in[12];

    float *x, *sv, *tb;
    bf16 *P;
    fp16 *xh,*qk,*aw,*hb,*Wq,*W1f,*W2f;
    cudaGetSymbolAddress((void**)&x,  g_x);
    cudaGetSymbolAddress((void**)&sv, g_sv);
    cudaGetSymbolAddress((void**)&tb, g_t);
    cudaGetSymbolAddress((void**)&P,  g_P);
    cudaGetSymbolAddress((void**)&xh, g_xh);
    cudaGetSymbolAddress((void**)&qk, g_qk);
    cudaGetSymbolAddress((void**)&aw, g_aw);
    cudaGetSymbolAddress((void**)&hb, g_h);
    cudaGetSymbolAddress((void**)&Wq, g_Wq);
    cudaGetSymbolAddress((void**)&W1f,g_W1);
    cudaGetSymbolAddress((void**)&W2f,g_W2);

    cudaFuncSetAttribute(attn_exp, cudaFuncAttributeMaxDynamicSharedMemorySize, ATTN_SMEM);
    cudaFuncSetAttribute(mma_gemm2<0,0,1,0,0>, cudaFuncAttributeMaxDynamicSharedMemorySize, GEMM_SMEM);
    cudaFuncSetAttribute(mma_gemm2<0,1,0,1,1>, cudaFuncAttributeMaxDynamicSharedMemorySize, GEMM_SMEM);
    cudaFuncSetAttribute(mma_gemm2<1,0,1,0,0>, cudaFuncAttributeMaxDynamicSharedMemorySize, GEMM_SMEM);
    cudaFuncSetAttribute(mma_gemm2<0,1,0,0,1>, cudaFuncAttributeMaxDynamicSharedMemorySize, GEMM_SMEM);

    // one-time merged quantization (weights + input)
    quant_all<<<(QUANT_TOTAL + 255)/256, 256>>>(Wqkv, W1, W2, input,
                                                Wq, W1f, W2f, x, xh);

    for (int d = 0; d < 4; d++){
        const float* bq = bqkv + (size_t)d * 1536;

        // q|k projection -> fp16 qk (v/out-proj of Wqkv are dead in the reference)
        mma_gemm2<0,0,1,0,0><<<dim3(1024/256, Mq/128, 1), 256, GEMM_SMEM>>>(
            xh, Wq + (size_t)d*1024*512,
            bq, nullptr, nullptr, qk, Mq, 1024, 512, 0, 0, 0, 0);

        // fused logits+exp (stores causal bf16 P, computes sinv)
        attn_exp<<<dim3(Bq*Hq, Lq/128), 256, ATTN_SMEM>>>(qk, P, sv);

        // fused head-average + second softmax -> fp16 attention weights
        make_w2<<<Bq*Lq, 256>>>(P, sv, aw);

        // tb = x + W @ x : NN GEMM (trans-ldmatrix B), residual fused in epilogue
        mma_gemm2<0,1,0,1,1><<<dim3(Eq/256, Lq/128, Bq), 256, GEMM_SMEM>>>(
            aw, xh, nullptr, x, tb, nullptr,
            Lq, Eq, Lq, (long)Lq*Lq, (long)Lq*Eq, (long)Lq*Eq, 1);

        // x = LN2(LN1(tb))  (cross-attn block is a double-LN no-op)
        ln2<1><<<Mq/8, 256>>>(tb,
                              g1 + d*Eq, bt1 + d*Eq,
                              g2 + d*Eq, bt2 + d*Eq, x, xh);

        // FFN1 -> fp16 h (relu); FFN2 -> tb = x + ffn (residual fused)
        mma_gemm2<1,0,1,0,0><<<dim3(FFq/256, Mq/128, 1), 256, GEMM_SMEM>>>(
            xh, W1f + (size_t)d*2048*512,
            b1 + (size_t)d*FFq, nullptr, nullptr, hb, Mq, FFq, Eq, 0, 0, 0, 0);
        mma_gemm2<0,1,0,0,1><<<dim3(Eq/256, Mq/128, 1), 256, GEMM_SMEM>>>(
            hb, W2f + (size_t)d*512*2048,
            b2 + (size_t)d*Eq, x, tb, nullptr, Mq, Eq, FFq, 0, 0, 0, 0);

        if (d == 3)
            ln1<0><<<Mq/8, 256>>>(tb, g3 + d*Eq, bt3 + d*Eq,
                                  (float*)d_out, nullptr);
        else
            ln1<1><<<Mq/8, 256>>>(tb, g3 + d*Eq, bt3 + d*Eq, x, xh);
    }
}

// round 15
// speedup vs baseline: 1.1004x; 1.0425x over previous
#include <cuda_runtime.h>
#include <cuda_fp16.h>
#include <cuda_bf16.h>
#include <math.h>
#include <stdint.h>

// Problem constants
#define Bq   8
#define Lq   1024
#define Eq   512
#define Hq   8
#define FFq  2048
#define Mq   (Bq*Lq)          // 8192 tokens

typedef __half        fp16;
typedef __nv_bfloat16 bf16;

// ---------------- scratch (static device globals; allocation-free) ----------
__device__ float g_x [Mq*Eq];        // current activations (fp32, residual path)
__device__ float g_sv[Bq*Hq*Lq];     // per-(b,h,i) 0.125/sum(exp)
__device__ float g_t [Mq*Eq];        // x + (sa|ffn) pre-LN sum (fp32)
__device__ bf16  g_P [(size_t)Bq*Hq*Lq*Lq];  // per-head exp(logits), bf16, causal tiles

// fp16 buffers (plain quantized)
__device__ fp16 g_xh [Mq*Eq];
__device__ fp16 g_qk [Mq*1024];
__device__ fp16 g_aw [(size_t)Bq*Lq*Lq];
__device__ fp16 g_h  [Mq*FFq];
__device__ fp16 g_Wq [4*1024*512];
__device__ fp16 g_W1 [4*2048*512];
__device__ fp16 g_W2 [4*512*2048];

// ---------------- helpers ------------------------------------------------------
__device__ __forceinline__ float warp_sum(float s){
    #pragma unroll
    for (int o=16;o;o>>=1) s += __shfl_xor_sync(0xffffffffu, s, o);
    return s;
}
__device__ __forceinline__ uint32_t hquant(float x0, float x1){
    return (uint32_t)__half_as_ushort(__float2half_rn(x0)) |
           ((uint32_t)__half_as_ushort(__float2half_rn(x1)) << 16);
}
__device__ __forceinline__ uint32_t bpack(float x0, float x1){
    __nv_bfloat162 b = __floats2bfloat162_rn(x0, x1);
    return *(uint32_t*)&b;
}
__device__ __forceinline__ uint32_t smem_u32(const void* p){
    uint32_t a;
    asm("{ .reg .u64 t; cvta.to.shared.u64 t, %1; cvt.u32.u64 %0, t; }" : "=r"(a) : "l"(p));
    return a;
}
__device__ __forceinline__ void cp16(uint32_t dst, const void* src){
    asm volatile("cp.async.cg.shared.global [%0], [%1], 16;" :: "r"(dst), "l"(src));
}
#define CP_COMMIT() asm volatile("cp.async.commit_group;" ::: "memory")
#define CP_WAIT0()  asm volatile("cp.async.wait_group 0;" ::: "memory")
#define CP_WAIT1()  asm volatile("cp.async.wait_group 1;" ::: "memory")

#define LDSM_X4(r, addr) \
    asm volatile("ldmatrix.sync.aligned.m8n8.x4.shared.b16 {%0,%1,%2,%3}, [%4];" \
        : "=r"((r)[0]), "=r"((r)[1]), "=r"((r)[2]), "=r"((r)[3]) : "r"(addr))
#define LDSM_X4_T(r, addr) \
    asm volatile("ldmatrix.sync.aligned.m8n8.x4.trans.shared.b16 {%0,%1,%2,%3}, [%4];" \
        : "=r"((r)[0]), "=r"((r)[1]), "=r"((r)[2]), "=r"((r)[3]) : "r"(addr))

__device__ __forceinline__ void mma16816(float* c, const uint32_t* a, const uint32_t* b){
    asm volatile(
        "mma.sync.aligned.m16n8k16.row.col.f32.f16.f16.f32 "
        "{%0,%1,%2,%3}, {%4,%5,%6,%7}, {%8,%9}, {%0,%1,%2,%3};\n"
        : "+f"(c[0]), "+f"(c[1]), "+f"(c[2]), "+f"(c[3])
        : "r"(a[0]), "r"(a[1]), "r"(a[2]), "r"(a[3]), "r"(b[0]), "r"(b[1]));
}

// ============================================================================
// Merged one-time quantization: Wqkv(q|k slices), W1, W2, input copy+quant
// ============================================================================
__global__ __launch_bounds__(256) void quant_all(
    const float* __restrict__ Wqkv, const float* __restrict__ W1,
    const float* __restrict__ W2,   const float* __restrict__ input,
    fp16* __restrict__ Wq, fp16* __restrict__ W1f, fp16* __restrict__ W2f,
    float* __restrict__ x, fp16* __restrict__ xh)
{
    const int nWq = 4*1024*512/4;
    const int nW  = 4*2048*512/4;
    const int nx  = Mq*Eq/4;
    int i = blockIdx.x*256 + threadIdx.x;
    if (i < nWq){
        const int per = 1024*512/4;
        int d = i / per, r = i - d*per;
        float4 v = ((const float4*)(Wqkv + (size_t)d*1536*512))[r];
        ((uint2*)(Wq + (size_t)d*1024*512))[r] =
            make_uint2(hquant(v.x, v.y), hquant(v.z, v.w));
        return;
    }
    i -= nWq;
    if (i < nW){
        float4 v = ((const float4*)W1)[i];
        ((uint2*)W1f)[i] = make_uint2(hquant(v.x, v.y), hquant(v.z, v.w));
        return;
    }
    i -= nW;
    if (i < nW){
        float4 v = ((const float4*)W2)[i];
        ((uint2*)W2f)[i] = make_uint2(hquant(v.x, v.y), hquant(v.z, v.w));
        return;
    }
    i -= nW;
    if (i < nx){
        float4 v = ((const float4*)input)[i];
        ((float4*)x)[i] = v;
        ((uint2*)xh)[i] = make_uint2(hquant(v.x, v.y), hquant(v.z, v.w));
    }
}
#define QUANT_TOTAL (4*1024*512/4 + 2*(4*2048*512/4) + Mq*Eq/4)

// ============================================================================
// Tensor-core GEMM, fp16 x fp16, fp32 accumulate.
// Tile 128(M) x 128(N), BK=32, 256 threads (2x4 warps, 64x32 each),
// 2 CTAs/SM, 3-stage cp.async ring, single __syncthreads per chunk,
// ldmatrix fragments.
// TRB=0: C = A[M,K] * B[N,K]^T ; TRB=1: C = A[M,K] * B[K,N] (trans ldmatrix)
// ADDR=1: C += Rres fused in epilogue.
// ============================================================================
#define SA_U32   2560                   // A stage: 128 rows * 20 u32
#define SB_U32   2560                   // B stage: NT 128 rows*20 u32 (TRB 32*68=2176 < 2560)
#define STG_U32  (SA_U32 + SB_U32)      // 5120
#define GEMM_SMEM (3 * STG_U32 * 4)     // 61440 B  (2 CTAs/SM)

template<int RELU, int WF32, int WH16, int TRB, int ADDR>
__global__ __launch_bounds__(256, 2) void mma_gemm2(
    const fp16* __restrict__ Ah, const fp16* __restrict__ Bh,
    const float* __restrict__ bias, const float* __restrict__ Rres,
    float* __restrict__ C, fp16* __restrict__ Ch,
    int M, int N, int K, long sA, long sB, long sC, int causal)
{
    extern __shared__ uint32_t sg[];
    const int bm = blockIdx.y * 128, bn = blockIdx.x * 128;
    const fp16* Abh = Ah + (size_t)blockIdx.z * sA;
    const fp16* Bbh = Bh + (size_t)blockIdx.z * sB;

    const int t    = threadIdx.x;
    const int lane = t & 31, wid = t >> 5;
    const int wm   = wid >> 2, wn = wid & 3;
    const int gid  = lane >> 2, tig = lane & 3;
    const int fr   = t >> 1, half = t & 1;

    float acc[4][4][4];
    #pragma unroll
    for (int i=0;i<4;i++)
        #pragma unroll
        for (int j=0;j<4;j++)
            #pragma unroll
            for (int q=0;q<4;q++) acc[i][j][q] = 0.f;

    const uint32_t sbase = smem_u32(sg);
    const uint32_t da = sbase + (uint32_t)(fr*80) + (uint32_t)half*32;
    const fp16* ga = Abh + (size_t)(bm+fr)*K + half*16;

    // NT B fill: 128 rows x 64B
    const uint32_t db = sbase + (uint32_t)(SA_U32*4) + (uint32_t)(fr*80) + (uint32_t)half*32;
    const fp16* gb = Bbh + (size_t)(bn+fr)*K + half*16;

    // TRB B fill: 32 k-rows x 256B (+16B pad -> 272B stride); thread t: row t>>3, 32B at (t&7)*32
    const uint32_t dbt = sbase + (uint32_t)(SA_U32*4) + (uint32_t)((t>>3)*272) + (uint32_t)(t&7)*32;
    const fp16* gbt = Bbh + (size_t)(t>>3)*N + bn + (t&7)*16;

    // ldmatrix bases
    const uint32_t aB = sbase + (uint32_t)((wm*64 + (lane & 15))*80) + (uint32_t)(lane >> 4)*16;
    const uint32_t bB = sbase + (uint32_t)(SA_U32*4) +
        (uint32_t)((wn*32 + ((lane >> 4) << 3) + (lane & 7))*80) +
        (uint32_t)((lane >> 3) & 1)*16;
    const uint32_t bBt = sbase + (uint32_t)(SA_U32*4) +
        (uint32_t)((((lane >> 3) & 1)*8 + (lane & 7))*272) +
        (uint32_t)(lane >> 4)*16 + (uint32_t)wn*64;

    const int kend = causal ? (bm + 128) : K;
    const int nch  = kend >> 5;

    #define G_ISSUE(ch_) do{ \
        const uint32_t st_ = (uint32_t)((ch_) % 3) * (STG_U32*4); \
        const fp16* A0_ = ga + ((ch_) << 5); \
        cp16(da + st_, A0_);  cp16(da + st_ + 16, A0_ + 8); \
        if (TRB){ \
            const fp16* BT_ = gbt + (size_t)((ch_) << 5) * N; \
            cp16(dbt + st_, BT_);  cp16(dbt + st_ + 16, BT_ + 8); \
        } else { \
            const fp16* B0_ = gb + ((ch_) << 5); \
            cp16(db + st_, B0_);  cp16(db + st_ + 16, B0_ + 8); \
        } \
        CP_COMMIT(); }while(0)

    if (nch > 0) G_ISSUE(0);
    if (nch > 1) G_ISSUE(1);

    for (int ch = 0; ch < nch; ch++){
        if (ch + 1 < nch) CP_WAIT1(); else CP_WAIT0();
        __syncthreads();                 // stage ch visible; prior compute done
        if (ch + 2 < nch) G_ISSUE(ch+2); // overwrites stage read 2 iters ago

        const uint32_t so = (uint32_t)(ch % 3) * (STG_U32*4);
        #pragma unroll
        for (int ks=0; ks<2; ks++){
            uint32_t ah[4][4], bf[2][4];
            #pragma unroll
            for (int mi=0;mi<4;mi++)
                LDSM_X4(ah[mi], aB + so + (uint32_t)mi*(16*80) + (uint32_t)ks*32);
            #pragma unroll
            for (int np=0;np<2;np++){
                if (TRB) LDSM_X4_T(bf[np], bBt + so + (uint32_t)np*32 + (uint32_t)ks*(16*272));
                else     LDSM_X4  (bf[np], bB  + so + (uint32_t)np*(16*80) + (uint32_t)ks*32);
            }
            #pragma unroll
            for (int mi=0;mi<4;mi++){
                #pragma unroll
                for (int ni=0;ni<4;ni++){
                    uint32_t bb[2] = { bf[ni>>1][(ni&1)*2], bf[ni>>1][(ni&1)*2+1] };
                    mma16816(acc[mi][ni], ah[mi], bb);
                }
            }
        }
    }
    #undef G_ISSUE

    float*       Cb  = WF32 ? C    + (size_t)blockIdx.z * sC : nullptr;
    fp16*        Chb = WH16 ? Ch   + (size_t)blockIdx.z * sC : nullptr;
    const float* Rb  = ADDR ? Rres + (size_t)blockIdx.z * sC : nullptr;
    #pragma unroll
    for (int mi=0;mi<4;mi++){
        int row = bm + wm*64 + mi*16 + gid;
        #pragma unroll
        for (int ni=0;ni<4;ni++){
            int col = bn + wn*32 + ni*8 + tig*2;
            float2 v0 = make_float2(acc[mi][ni][0], acc[mi][ni][1]);
            float2 v1 = make_float2(acc[mi][ni][2], acc[mi][ni][3]);
            if (bias){
                float2 bb = *(const float2*)(bias + col);
                v0.x += bb.x; v0.y += bb.y; v1.x += bb.x; v1.y += bb.y;
            }
            if (RELU){
                v0.x=fmaxf(v0.x,0.f); v0.y=fmaxf(v0.y,0.f);
                v1.x=fmaxf(v1.x,0.f); v1.y=fmaxf(v1.y,0.f);
            }
            if (ADDR){
                float2 r0 = *(const float2*)(Rb + (size_t)row    *N + col);
                float2 r1 = *(const float2*)(Rb + (size_t)(row+8)*N + col);
                v0.x += r0.x; v0.y += r0.y; v1.x += r1.x; v1.y += r1.y;
            }
            if (WF32){
                *(float2*)(Cb + (size_t)row    *N + col) = v0;
                *(float2*)(Cb + (size_t)(row+8)*N + col) = v1;
            }
            if (WH16){
                *(uint32_t*)(Chb + (size_t)row    *N + col) = hquant(v0.x, v0.y);
                *(uint32_t*)(Chb + (size_t)(row+8)*N + col) = hquant(v1.x, v1.y);
            }
        }
    }
}

// ============================================================================
// Fused attention exp kernel, fp16, 3-stage cp.async K ring, ldmatrix frags
// ============================================================================
#define ATTN_SMEM (4*4608*4)
__global__ __launch_bounds__(256) void attn_exp(
    const fp16* __restrict__ qk,
    bf16* __restrict__ P, float* __restrict__ sinv)
{
    extern __shared__ uint32_t smx[];
    uint32_t* sQh = smx;
    uint32_t* sK  = smx + 4608;
    __shared__ float sred[128];

    const int bh = blockIdx.x;
    const int ti = blockIdx.y;
    const int i0 = ti * 128;
    const int b  = bh >> 3, h = bh & 7;
    const size_t qoff = (size_t)(b*Lq)*1024 + h*64;

    const int t = threadIdx.x;
    const int lane = t & 31, wid = t >> 5;
    const int wm = wid >> 2, wn = wid & 3;
    const int gid = lane >> 2, tig = lane & 3;
    const int fr = t >> 1, half = t & 1;

    if (t < 128) sred[t] = 0.f;

    const uint32_t dk = smem_u32(sK) + fr*144 + half*64;
    const fp16* gk = qk + qoff + 512 + (size_t)fr*1024 + half*32;

    #define K_ISSUE(jt_) do{ \
        const uint32_t st_ = (uint32_t)((jt_) % 3) * 18432; \
        const fp16* g_ = gk + (size_t)(jt_)*128*1024; \
        cp16(dk + st_,      g_);       cp16(dk + st_ + 16, g_ + 8); \
        cp16(dk + st_ + 32, g_ + 16);  cp16(dk + st_ + 48, g_ + 24); \
        CP_COMMIT(); }while(0)

    K_ISSUE(0);
    K_ISSUE(1);

    // load Q tile [128 x 64]
    {
        const uint4* sh = (const uint4*)(qk + qoff + (size_t)(i0+fr)*1024 + half*32);
        uint4* dh = (uint4*)(sQh + fr*36 + half*16);
        dh[0]=sh[0]; dh[1]=sh[1]; dh[2]=sh[2]; dh[3]=sh[3];
    }

    const uint32_t qB = smem_u32(sQh) +
        (uint32_t)((wm*64 + (lane & 15))*36)*4 + (uint32_t)(lane >> 4)*16;
    const uint32_t kB = smem_u32(sK) +
        (uint32_t)((wn*32 + ((lane >> 4) << 3) + (lane & 7))*36)*4 +
        (uint32_t)((lane >> 3) & 1)*16;

    float rsum[4][2];
    #pragma unroll
    for (int mi=0;mi<4;mi++){ rsum[mi][0]=0.f; rsum[mi][1]=0.f; }

    for (int jt = 0; jt < Lq/128; jt++){
        if (jt + 1 < Lq/128) CP_WAIT1(); else CP_WAIT0();
        __syncthreads();
        if (jt + 2 < Lq/128) K_ISSUE(jt+2);

        const uint32_t so = (uint32_t)(jt % 3) * 18432;
        float acc[4][4][4];
        #pragma unroll
        for (int i=0;i<4;i++)
            #pragma unroll
            for (int j=0;j<4;j++)
                #pragma unroll
                for (int q=0;q<4;q++) acc[i][j][q] = 0.f;

        #pragma unroll
        for (int ks=0; ks<4; ks++){
            uint32_t ah[4][4], bf[2][4];
            #pragma unroll
            for (int mi=0;mi<4;mi++)
                LDSM_X4(ah[mi], qB + (uint32_t)mi*(16*144) + (uint32_t)ks*32);
            #pragma unroll
            for (int np=0;np<2;np++)
                LDSM_X4(bf[np], kB + so + (uint32_t)np*(16*144) + (uint32_t)ks*32);
            #pragma unroll
            for (int mi=0;mi<4;mi++){
                #pragma unroll
                for (int ni=0;ni<4;ni++){
                    uint32_t bb[2] = { bf[ni>>1][(ni&1)*2], bf[ni>>1][(ni&1)*2+1] };
                    mma16816(acc[mi][ni], ah[mi], bb);
                }
            }
        }

        const int j0 = jt * 128;
        const bool store = (jt <= ti);
        #pragma unroll
        for (int mi=0;mi<4;mi++){
            const int row = i0 + wm*64 + mi*16 + gid;
            #pragma unroll
            for (int ni=0;ni<4;ni++){
                float e0 = __expf(acc[mi][ni][0] * 0.125f);
                float e1 = __expf(acc[mi][ni][1] * 0.125f);
                float e2 = __expf(acc[mi][ni][2] * 0.125f);
                float e3 = __expf(acc[mi][ni][3] * 0.125f);
                rsum[mi][0] += e0 + e1;
                rsum[mi][1] += e2 + e3;
                if (store){
                    const int col = j0 + wn*32 + ni*8 + tig*2;
                    bf16* p0 = P + ((size_t)bh*Lq + row)*Lq + col;
                    *(uint32_t*)p0          = bpack(e0, e1);
                    *(uint32_t*)(p0 + 8*Lq) = bpack(e2, e3);
                }
            }
        }
    }
    #undef K_ISSUE

    #pragma unroll
    for (int mi=0;mi<4;mi++){
        float r0 = rsum[mi][0], r1 = rsum[mi][1];
        r0 += __shfl_xor_sync(0xffffffffu, r0, 1);
        r0 += __shfl_xor_sync(0xffffffffu, r0, 2);
        r1 += __shfl_xor_sync(0xffffffffu, r1, 1);
        r1 += __shfl_xor_sync(0xffffffffu, r1, 2);
        if (tig == 0){
            atomicAdd(&sred[wm*64 + mi*16 + gid    ], r0);
            atomicAdd(&sred[wm*64 + mi*16 + gid + 8], r1);
        }
    }
    __syncthreads();
    if (t < 128)
        sinv[(size_t)bh*Lq + i0 + t] = 0.125f / sred[t];
}

// ============================================================================
// Fused head-average + second softmax -> fp16 W
// ============================================================================
__global__ __launch_bounds__(256) void make_w2(
    const bf16* __restrict__ P, const float* __restrict__ sinv,
    fp16* __restrict__ Wh)
{
    const int row = blockIdx.x;            // b*1024 + i
    const int b = row >> 10, i = row & 1023;
    const int t = threadIdx.x;
    __shared__ float sv8[8];
    if (t < 8) sv8[t] = sinv[(size_t)(b*8 + t)*Lq + i];
    __syncthreads();

    const int j0 = t*4;
    float v[4] = {0.f,0.f,0.f,0.f};
    float s = 0.f;
    if (j0 <= i){
        float a[4] = {0.f,0.f,0.f,0.f};
        const bf16* pb = P + ((size_t)(b*8)*Lq + i)*Lq + j0;
        #pragma unroll
        for (int h=0; h<8; h++){
            const uint2 pv = *(const uint2*)(pb + (size_t)h*Lq*Lq);
            const float sc = sv8[h];
            float2 f0 = __bfloat1622float2(*(const __nv_bfloat162*)&pv.x);
            float2 f1 = __bfloat1622float2(*(const __nv_bfloat162*)&pv.y);
            a[0] = fmaf(f0.x, sc, a[0]); a[1] = fmaf(f0.y, sc, a[1]);
            a[2] = fmaf(f1.x, sc, a[2]); a[3] = fmaf(f1.y, sc, a[3]);
        }
        #pragma unroll
        for (int u=0;u<4;u++){
            int j = j0 + u;
            if (j <= i){
                float pos = __expf((float)(j - i) * 0.1f);
                v[u] = __expf(a[u] + pos);
                s += v[u];
            }
        }
    }
    s = warp_sum(s);
    __shared__ float red[8];
    if ((t & 31) == 0) red[t >> 5] = s;
    __syncthreads();
    float tot = 0.f;
    #pragma unroll
    for (int w=0;w<8;w++) tot += red[w];
    float inv = 1.f / tot;
    *(uint2*)(Wh + (size_t)row*Lq + j0) =
        make_uint2(hquant(v[0]*inv, v[1]*inv), hquant(v[2]*inv, v[3]*inv));
}

// ============================================================================
// LayerNorm kernels (one warp per 512-wide row); single pre-summed input z.
// ============================================================================
template<int WH>
__global__ __launch_bounds__(256) void ln2(
    const float* __restrict__ z,
    const float* __restrict__ g1, const float* __restrict__ b1,
    const float* __restrict__ g2, const float* __restrict__ b2,
    float* __restrict__ out, fp16* __restrict__ oh)
{
    const int row  = blockIdx.x * 8 + (threadIdx.x >> 5);
    const int lane = threadIdx.x & 31;
    const float* zr = z + (size_t)row * Eq;
    float v[16]; float s = 0.f;
    #pragma unroll
    for (int u=0;u<16;u++){ int c = lane + u*32; v[u] = zr[c]; s += v[u]; }
    s = warp_sum(s);
    float mean = s * (1.0f/Eq);
    float sq = 0.f;
    #pragma unroll
    for (int u=0;u<16;u++){ float d = v[u]-mean; sq += d*d; }
    sq = warp_sum(sq);
    float rstd = rsqrtf(sq*(1.0f/Eq) + 1e-5f);
    float s2 = 0.f;
    #pragma unroll
    for (int u=0;u<16;u++){ int c = lane + u*32; v[u] = (v[u]-mean)*rstd*g1[c] + b1[c]; s2 += v[u]; }
    s2 = warp_sum(s2);
    float m2 = s2 * (1.0f/Eq);
    float q2 = 0.f;
    #pragma unroll
    for (int u=0;u<16;u++){ float d = v[u]-m2; q2 += d*d; }
    q2 = warp_sum(q2);
    float r2 = rsqrtf(q2*(1.0f/Eq) + 1e-5f);
    float* orow = out + (size_t)row * Eq;
    #pragma unroll
    for (int u=0;u<16;u++){
        int c = lane + u*32;
        float o = (v[u]-m2)*r2*g2[c] + b2[c];
        orow[c] = o;
        if (WH) oh[(size_t)row*Eq + c] = __float2half_rn(o);
    }
}

template<int WH>
__global__ __launch_bounds__(256) void ln1(
    const float* __restrict__ z,
    const float* __restrict__ g, const float* __restrict__ b,
    float* __restrict__ out, fp16* __restrict__ oh)
{
    const int row  = blockIdx.x * 8 + (threadIdx.x >> 5);
    const int lane = threadIdx.x & 31;
    const float* zr = z + (size_t)row * Eq;
    float v[16]; float s = 0.f;
    #pragma unroll
    for (int u=0;u<16;u++){ int c = lane + u*32; v[u] = zr[c]; s += v[u]; }
    s = warp_sum(s);
    float mean = s * (1.0f/Eq);
    float sq = 0.f;
    #pragma unroll
    for (int u=0;u<16;u++){ float d = v[u]-mean; sq += d*d; }
    sq = warp_sum(sq);
    float rstd = rsqrtf(sq*(1.0f/Eq) + 1e-5f);
    float* orow = out + (size_t)row * Eq;
    #pragma unroll
    for (int u=0;u<16;u++){
        int c = lane + u*32;
        float o = (v[u]-mean)*rstd*g[c] + b[c];
        orow[c] = o;
        if (WH) oh[(size_t)row*Eq + c] = __float2half_rn(o);
    }
}

// ============================================================================
// Launch
// ============================================================================
extern "C" void kernel_launch(void* const* d_in, const int* in_sizes, int n_in,
                              void* d_out, int out_size)
{
    const float* input = (const float*)d_in[0];
    const float* Wqkv  = (const float*)d_in[1];
    const float* bqkv  = (const float*)d_in[2];
    const float* W1    = (const float*)d_in[3];
    const float* b1    = (const float*)d_in[4];
    const float* W2    = (const float*)d_in[5];
    const float* b2    = (const float*)d_in[6];
    const float* g1    = (const float*)d_in[7];
    const float* bt1   = (const float*)d_in[8];
    const float* g2    = (const float*)d_in[9];
    const float* bt2   = (const float*)d_in[10];
    const float* g3    = (const float*)d_in[11];
    const float* bt3   = (const float*)d_in[12];

    float *x, *sv, *tb;
    bf16 *P;
    fp16 *xh,*qk,*aw,*hb,*Wq,*W1f,*W2f;
    cudaGetSymbolAddress((void**)&x,  g_x);
    cudaGetSymbolAddress((void**)&sv, g_sv);
    cudaGetSymbolAddress((void**)&tb, g_t);
    cudaGetSymbolAddress((void**)&P,  g_P);
    cudaGetSymbolAddress((void**)&xh, g_xh);
    cudaGetSymbolAddress((void**)&qk, g_qk);
    cudaGetSymbolAddress((void**)&aw, g_aw);
    cudaGetSymbolAddress((void**)&hb, g_h);
    cudaGetSymbolAddress((void**)&Wq, g_Wq);
    cudaGetSymbolAddress((void**)&W1f,g_W1);
    cudaGetSymbolAddress((void**)&W2f,g_W2);

    cudaFuncSetAttribute(attn_exp, cudaFuncAttributeMaxDynamicSharedMemorySize, ATTN_SMEM);
    cudaFuncSetAttribute(mma_gemm2<0,0,1,0,0>, cudaFuncAttributeMaxDynamicSharedMemorySize, GEMM_SMEM);
    cudaFuncSetAttribute(mma_gemm2<0,1,0,1,1>, cudaFuncAttributeMaxDynamicSharedMemorySize, GEMM_SMEM);
    cudaFuncSetAttribute(mma_gemm2<1,0,1,0,0>, cudaFuncAttributeMaxDynamicSharedMemorySize, GEMM_SMEM);
    cudaFuncSetAttribute(mma_gemm2<0,1,0,0,1>, cudaFuncAttributeMaxDynamicSharedMemorySize, GEMM_SMEM);

    // one-time merged quantization (weights + input)
    quant_all<<<(QUANT_TOTAL + 255)/256, 256>>>(Wqkv, W1, W2, input,
                                                Wq, W1f, W2f, x, xh);

    for (int d = 0; d < 4; d++){
        const float* bq = bqkv + (size_t)d * 1536;

        // q|k projection -> fp16 qk (v/out-proj of Wqkv are dead in the reference)
        mma_gemm2<0,0,1,0,0><<<dim3(1024/128, Mq/128, 1), 256, GEMM_SMEM>>>(
            xh, Wq + (size_t)d*1024*512,
            bq, nullptr, nullptr, qk, Mq, 1024, 512, 0, 0, 0, 0);

        // fused logits+exp (stores causal bf16 P, computes sinv)
        attn_exp<<<dim3(Bq*Hq, Lq/128), 256, ATTN_SMEM>>>(qk, P, sv);

        // fused head-average + second softmax -> fp16 attention weights
        make_w2<<<Bq*Lq, 256>>>(P, sv, aw);

        // tb = x + W @ x : NN GEMM (trans-ldmatrix B), residual fused in epilogue
        mma_gemm2<0,1,0,1,1><<<dim3(Eq/128, Lq/128, Bq), 256, GEMM_SMEM>>>(
            aw, xh, nullptr, x, tb, nullptr,
            Lq, Eq, Lq, (long)Lq*Lq, (long)Lq*Eq, (long)Lq*Eq, 1);

        // x = LN2(LN1(tb))  (cross-attn block is a double-LN no-op)
        ln2<1><<<Mq/8, 256>>>(tb,
                              g1 + d*Eq, bt1 + d*Eq,
                              g2 + d*Eq, bt2 + d*Eq, x, xh);

        // FFN1 -> fp16 h (relu); FFN2 -> tb = x + ffn (residual fused)
        mma_gemm2<1,0,1,0,0><<<dim3(FFq/128, Mq/128, 1), 256, GEMM_SMEM>>>(
            xh, W1f + (size_t)d*2048*512,
            b1 + (size_t)d*FFq, nullptr, nullptr, hb, Mq, FFq, Eq, 0, 0, 0, 0);
        mma_gemm2<0,1,0,0,1><<<dim3(Eq/128, Mq/128, 1), 256, GEMM_SMEM>>>(
            hb, W2f + (size_t)d*512*2048,
            b2 + (size_t)d*Eq, x, tb, nullptr, Mq, Eq, FFq, 0, 0, 0, 0);

        if (d == 3)
            ln1<0><<<Mq/8, 256>>>(tb, g3 + d*Eq, bt3 + d*Eq,
                                  (float*)d_out, nullptr);
        else
            ln1<1><<<Mq/8, 256>>>(tb, g3 + d*Eq, bt3 + d*Eq, x, xh);
    }
}